// round 14
// baseline (speedup 1.0000x reference)
#include <cuda_runtime.h>
#include <cuda_bf16.h>
#include <cuda_fp16.h>
#include <cstdint>

#define C_     192
#define C3     576
#define NHEADS 6
#define HD     32
#define HH_    256
#define WW_    256
#define HW_    65536
#define BATCH  2
#define KDIM   192
#define M1     576
#define M1PAD  640
#define M2     192
#define M2PAD  256

#define GR_CHUNKS 64           // 64 chunks x 4 rows = 256 image rows
#define ROWS_PC   4

// GEMM tiling (fp16 2-product: A hi/lo tiles + single B tile)
#define BM 128
#define BN 128
#define BK 32
#define APITCH 80              // bytes per A smem row (64B data + 16B pad)
#define BPITCH 272             // bytes per B smem row (256B data + 16B pad)
#define ATILE (BM * APITCH)    // 10240
#define BTILE (BK * BPITCH)    // 8704
#define BUFSZ (2 * ATILE + BTILE)      // 29184
#define GSMEM (2 * BUFSZ)              // 58368
#define NITER 6                        // 192/32 k-tiles

// dwgram tiles: 4 bf16 tiles [32ch][256px], pitch 528B
#define QP_B 528
#define DG_SMEM (4 * 32 * QP_B)        // 67584 B

// ---------------- scratch (device globals) -----------------------------------
__device__ float g_qkv[BATCH * C3 * HW_];
__device__ __half g_x_h[BATCH * KDIM * HW_];          // x single fp16 [b][k][n]
__device__ __half g_v_h[BATCH * KDIM * HW_];          // v single fp16
__device__ __half g_A1_h[M1PAD * KDIM];               // w_qkv fp16 hi (pad rows zero)
__device__ __half g_A1_l[M1PAD * KDIM];               // w_qkv fp16 lo
__device__ __half g_A2_h[BATCH * M2PAD * KDIM];       // M_eff fp16 hi
__device__ __half g_A2_l[BATCH * M2PAD * KDIM];       // M_eff fp16 lo
__device__ float g_gram_part[GR_CHUNKS * BATCH * NHEADS * HD * HD];
__device__ float g_qsq_part [GR_CHUNKS * BATCH * NHEADS * HD];
__device__ float g_ksq_part [GR_CHUNKS * BATCH * NHEADS * HD];
__device__ float g_attn[BATCH * NHEADS * HD * HD];

// ---------------- PTX helpers (sm_80+ only) ----------------------------------
__device__ __forceinline__ uint32_t smem_u32(const void* p) {
    uint32_t a;
    asm("{ .reg .u64 t; cvta.to.shared.u64 t, %1; cvt.u32.u64 %0, t; }" : "=r"(a) : "l"(p));
    return a;
}
#define CP_ASYNC16(dst, src) \
    asm volatile("cp.async.cg.shared.global [%0], [%1], 16;" :: "r"(dst), "l"(src))
#define CP_COMMIT() asm volatile("cp.async.commit_group;" ::: "memory")
#define CP_WAIT(n)  asm volatile("cp.async.wait_group %0;" :: "n"(n) : "memory")

#define LDM_X4(r, addr) \
    asm volatile("ldmatrix.sync.aligned.m8n8.x4.shared.b16 {%0,%1,%2,%3}, [%4];" \
        : "=r"((r)[0]), "=r"((r)[1]), "=r"((r)[2]), "=r"((r)[3]) : "r"(addr))
#define LDM_X2T(r, addr) \
    asm volatile("ldmatrix.sync.aligned.m8n8.x2.trans.shared.b16 {%0,%1}, [%2];" \
        : "=r"((r)[0]), "=r"((r)[1]) : "r"(addr))

// bf16 mma (dwgram)
__device__ __forceinline__ void mma16816(float* d, const uint32_t* a, const uint32_t* b) {
    asm volatile(
        "mma.sync.aligned.m16n8k16.row.col.f32.bf16.bf16.f32 "
        "{%0,%1,%2,%3}, {%4,%5,%6,%7}, {%8,%9}, {%0,%1,%2,%3};"
        : "+f"(d[0]), "+f"(d[1]), "+f"(d[2]), "+f"(d[3])
        : "r"(a[0]), "r"(a[1]), "r"(a[2]), "r"(a[3]), "r"(b[0]), "r"(b[1]));
}
// fp16 mma (big GEMMs)
__device__ __forceinline__ void mma16816h(float* d, const uint32_t* a, const uint32_t* b) {
    asm volatile(
        "mma.sync.aligned.m16n8k16.row.col.f32.f16.f16.f32 "
        "{%0,%1,%2,%3}, {%4,%5,%6,%7}, {%8,%9}, {%0,%1,%2,%3};"
        : "+f"(d[0]), "+f"(d[1]), "+f"(d[2]), "+f"(d[3])
        : "r"(a[0]), "r"(a[1]), "r"(a[2]), "r"(a[3]), "r"(b[0]), "r"(b[1]));
}

// pack 8 fp32 -> 8 fp16 (uint4)
__device__ __forceinline__ uint4 pack8h(const float4& a, const float4& b) {
    __half2 p0 = __halves2half2(__float2half_rn(a.x), __float2half_rn(a.y));
    __half2 p1 = __halves2half2(__float2half_rn(a.z), __float2half_rn(a.w));
    __half2 p2 = __halves2half2(__float2half_rn(b.x), __float2half_rn(b.y));
    __half2 p3 = __halves2half2(__float2half_rn(b.z), __float2half_rn(b.w));
    return make_uint4(*reinterpret_cast<uint32_t*>(&p0), *reinterpret_cast<uint32_t*>(&p1),
                      *reinterpret_cast<uint32_t*>(&p2), *reinterpret_cast<uint32_t*>(&p3));
}

// ---------------------------------------------------------------------------
// fp16 2-product GEMM (A-split): C = A*B.
// A fp16 hi/lo [Mpad][192]; B single fp16 [192][HW].
// Products: Ah*B + Al*B  (error ~ A*(B-Bh) ~ 2^-12 relative).
// ---------------------------------------------------------------------------
__global__ __launch_bounds__(256, 2) void gemm_ah2(
    const __half* __restrict__ Ah, const __half* __restrict__ Al,
    const __half* __restrict__ B,
    float* __restrict__ C, int Mvalid, long aBatch, long cBatch)
{
    extern __shared__ char smem[];
    const uint32_t sb = smem_u32(smem);

    const int tid  = threadIdx.x;
    const int wid  = tid >> 5;
    const int lane = tid & 31;
    const int wm   = wid >> 2;       // 0..1  (64 rows)
    const int wn   = wid & 3;        // 0..3  (32 cols)

    const int bz = blockIdx.z;
    const int m0 = blockIdx.x * BM;
    const int n0 = blockIdx.y * BN;

    Ah += (long)bz * aBatch;  Al += (long)bz * aBatch;
    B  += (long)bz * KDIM * HW_;
    C  += (long)bz * cBatch;

    float acc[4][4][4];
    #pragma unroll
    for (int i = 0; i < 4; i++)
        #pragma unroll
        for (int j = 0; j < 4; j++)
            #pragma unroll
            for (int r = 0; r < 4; r++) acc[i][j][r] = 0.f;

    auto loadTiles = [&](int it, int buf) {
        const int k0 = it * BK;
        const uint32_t base = sb + (uint32_t)buf * BUFSZ;
        #pragma unroll
        for (int i = 0; i < 2; i++) {
            const int ca = tid + 256 * i;          // 0..511
            const int ar = ca >> 2, as_ = ca & 3;
            const long goff = (long)(m0 + ar) * KDIM + k0 + as_ * 8;
            const uint32_t soff = ar * APITCH + as_ * 16;
            CP_ASYNC16(base + soff,          Ah + goff);
            CP_ASYNC16(base + ATILE + soff,  Al + goff);
            const int br = ca >> 4, bs_ = ca & 15;
            CP_ASYNC16(base + 2 * ATILE + br * BPITCH + bs_ * 16,
                       B + (long)(k0 + br) * HW_ + n0 + bs_ * 8);
        }
    };

    loadTiles(0, 0);
    CP_COMMIT();

    #pragma unroll 1
    for (int it = 0; it < NITER; it++) {
        if (it + 1 < NITER) {
            loadTiles(it + 1, (it + 1) & 1);
            CP_COMMIT();
            CP_WAIT(1);
        } else {
            CP_WAIT(0);
        }
        __syncthreads();

        const uint32_t base = sb + (uint32_t)(it & 1) * BUFSZ;
        const uint32_t aHb = base, aLb = base + ATILE;
        const uint32_t bBb = base + 2 * ATILE;

        #pragma unroll
        for (int kf = 0; kf < 2; kf++) {
            uint32_t aH[4][4], aL[4][4], b[4][2];
            #pragma unroll
            for (int i = 0; i < 4; i++) {
                const uint32_t ro = (uint32_t)(wm * 64 + i * 16 + (lane & 15)) * APITCH
                                  + kf * 32 + ((lane >> 4) << 4);
                LDM_X4(aH[i], aHb + ro);
                LDM_X4(aL[i], aLb + ro);
            }
            #pragma unroll
            for (int j = 0; j < 4; j++) {
                const uint32_t ro = (uint32_t)(kf * 16 + (lane & 15)) * BPITCH
                                  + (uint32_t)(wn * 32 + j * 8) * 2;
                LDM_X2T(b[j], bBb + ro);
            }
            #pragma unroll
            for (int i = 0; i < 4; i++)
                #pragma unroll
                for (int j = 0; j < 4; j++) {
                    mma16816h(acc[i][j], aH[i], b[j]);
                    mma16816h(acc[i][j], aL[i], b[j]);
                }
        }
        __syncthreads();
    }

    const int rw = m0 + wm * 64 + (lane >> 2);
    const int cw = n0 + wn * 32 + (lane & 3) * 2;
    #pragma unroll
    for (int i = 0; i < 4; i++) {
        #pragma unroll
        for (int j = 0; j < 4; j++) {
            const int row = rw + i * 16;
            const int col = cw + j * 8;
            if (row < Mvalid)
                *reinterpret_cast<float2*>(C + (long)row * HW_ + col) =
                    make_float2(acc[i][j][0], acc[i][j][1]);
            if (row + 8 < Mvalid)
                *reinterpret_cast<float2*>(C + (long)(row + 8) * HW_ + col) =
                    make_float2(acc[i][j][2], acc[i][j][3]);
        }
    }
}

// ---------------------------------------------------------------------------
// 4-pixel depthwise conv: rows y-1..y+1, x0..x0+3 (x0 % 4 == 0)
// ---------------------------------------------------------------------------
__device__ __forceinline__ void conv4(
    const float* __restrict__ plane, const float* __restrict__ w,
    int y, int x0, float out[4])
{
    out[0] = out[1] = out[2] = out[3] = 0.f;
    #pragma unroll
    for (int dy = -1; dy <= 1; dy++) {
        const int yy = y + dy;
        if (yy < 0 || yy >= HH_) continue;
        const float* row = plane + yy * WW_ + x0;
        const float4 m = *reinterpret_cast<const float4*>(row);
        const float lft = (x0 > 0)       ? row[-1] : 0.f;
        const float rgt = (x0 + 4 < 256) ? row[4]  : 0.f;
        const float w0 = w[(dy + 1) * 3 + 0];
        const float w1 = w[(dy + 1) * 3 + 1];
        const float w2 = w[(dy + 1) * 3 + 2];
        out[0] += w0 * lft + w1 * m.x + w2 * m.y;
        out[1] += w0 * m.x + w1 * m.y + w2 * m.z;
        out[2] += w0 * m.y + w1 * m.z + w2 * m.w;
        out[3] += w0 * m.z + w1 * m.w + w2 * rgt;
    }
}

// ---------------------------------------------------------------------------
// 8-pixel depthwise conv (used by dwv: consecutive threads = consecutive spans)
// ---------------------------------------------------------------------------
__device__ __forceinline__ void conv8(
    const float* __restrict__ plane, const float* __restrict__ w,
    int y, int x0, float out[8])
{
    #pragma unroll
    for (int i = 0; i < 8; i++) out[i] = 0.f;
    #pragma unroll
    for (int dy = -1; dy <= 1; dy++) {
        const int yy = y + dy;
        if (yy < 0 || yy >= HH_) continue;
        const float* row = plane + yy * WW_ + x0;
        const float4 a = *reinterpret_cast<const float4*>(row);
        const float4 b = *reinterpret_cast<const float4*>(row + 4);
        const float lft = (x0 > 0)       ? row[-1] : 0.f;
        const float rgt = (x0 + 8 < 256) ? row[8]  : 0.f;
        const float w0 = w[(dy + 1) * 3 + 0];
        const float w1 = w[(dy + 1) * 3 + 1];
        const float w2 = w[(dy + 1) * 3 + 2];
        out[0] += w0 * lft + w1 * a.x + w2 * a.y;
        out[1] += w0 * a.x + w1 * a.y + w2 * a.z;
        out[2] += w0 * a.y + w1 * a.z + w2 * a.w;
        out[3] += w0 * a.z + w1 * a.w + w2 * b.x;
        out[4] += w0 * a.w + w1 * b.x + w2 * b.y;
        out[5] += w0 * b.x + w1 * b.y + w2 * b.z;
        out[6] += w0 * b.y + w1 * b.z + w2 * b.w;
        out[7] += w0 * b.z + w1 * b.w + w2 * rgt;
    }
}

// ---------------------------------------------------------------------------
// Fused depthwise conv (q,k) + tensor-core Gram partials (bf16 3-product,
// verified round-8/11 — untouched).
// ---------------------------------------------------------------------------
__global__ __launch_bounds__(512, 2) void dwgram(
    const float* __restrict__ qkv, const float* __restrict__ wdw)
{
    extern __shared__ char smraw[];
    const uint32_t sb = smem_u32(smraw);
    const uint32_t qhb = sb;
    const uint32_t qlb = sb + 32 * QP_B;
    const uint32_t khb = sb + 2 * 32 * QP_B;
    const uint32_t klb = sb + 3 * 32 * QP_B;
    float* red = reinterpret_cast<float*>(smraw);

    const int bh = blockIdx.y;
    const int b = bh / NHEADS, h = bh % NHEADS;
    const int chunk = blockIdx.x;
    const int tid = threadIdx.x;
    const int lane = tid & 31;

    const int ch6 = tid >> 3;
    const int grp = tid & 7;
    const int c   = ch6 & 31;
    const int gch = (ch6 < 32) ? (h * HD + c) : (C_ + h * HD + c);
    const float* plane = qkv + ((long)b * C3 + gch) * HW_;
    float w[9];
    #pragma unroll
    for (int i = 0; i < 9; i++) w[i] = wdw[gch * 9 + i];
    const uint32_t dHo = (ch6 < 32 ? (qhb - sb) : (khb - sb)) + (uint32_t)c * QP_B;
    const uint32_t dLo = (ch6 < 32 ? (qlb - sb) : (klb - sb)) + (uint32_t)c * QP_B;

    const int wrp  = tid >> 5;
    const int half = wrp >> 3;
    const int slc  = wrp & 7;

    float acc[4][4];
    #pragma unroll
    for (int j = 0; j < 4; j++)
        #pragma unroll
        for (int r = 0; r < 4; r++) acc[j][r] = 0.f;
    float sq = 0.f;

    #pragma unroll 1
    for (int r = 0; r < ROWS_PC; r++) {
        const int y = chunk * ROWS_PC + r;
        __syncthreads();
        #pragma unroll
        for (int i = 0; i < 8; i++) {
            const int x0 = (grp + 8 * i) * 4;
            float o[4];
            conv4(plane, w, y, x0, o);
            sq += o[0]*o[0] + o[1]*o[1] + o[2]*o[2] + o[3]*o[3];
            const __nv_bfloat16 h0 = __float2bfloat16(o[0]);
            const __nv_bfloat16 h1 = __float2bfloat16(o[1]);
            const __nv_bfloat16 h2 = __float2bfloat16(o[2]);
            const __nv_bfloat16 h3 = __float2bfloat16(o[3]);
            uint2 ph, pl;
            __nv_bfloat162 t0(h0, h1), t1(h2, h3);
            ph.x = *reinterpret_cast<uint32_t*>(&t0);
            ph.y = *reinterpret_cast<uint32_t*>(&t1);
            __nv_bfloat162 u0(__float2bfloat16(o[0] - __bfloat162float(h0)),
                              __float2bfloat16(o[1] - __bfloat162float(h1)));
            __nv_bfloat162 u1(__float2bfloat16(o[2] - __bfloat162float(h2)),
                              __float2bfloat16(o[3] - __bfloat162float(h3)));
            pl.x = *reinterpret_cast<uint32_t*>(&u0);
            pl.y = *reinterpret_cast<uint32_t*>(&u1);
            *reinterpret_cast<uint2*>(smraw + dHo + x0 * 2) = ph;
            *reinterpret_cast<uint2*>(smraw + dLo + x0 * 2) = pl;
        }
        __syncthreads();

        #pragma unroll
        for (int c2 = 0; c2 < 2; c2++) {
            const uint32_t off = (uint32_t)(slc * 64 + c2 * 32);
            uint32_t aH[4], aL[4], bH[2][4], bL[2][4];
            const uint32_t ra = (uint32_t)(16 * half + (lane & 15)) * QP_B
                              + ((lane >> 4) << 4) + off;
            LDM_X4(aH, qhb + ra);
            LDM_X4(aL, qlb + ra);
            #pragma unroll
            for (int nt2 = 0; nt2 < 2; nt2++) {
                const uint32_t rb = (uint32_t)((lane & 7) + ((lane >> 4) << 3) + 16 * nt2) * QP_B
                                  + (((lane >> 3) & 1) << 4) + off;
                LDM_X4(bH[nt2], khb + rb);
                LDM_X4(bL[nt2], klb + rb);
            }
            #pragma unroll
            for (int nt = 0; nt < 4; nt++) {
                const uint32_t* bh_ = &bH[nt >> 1][(nt & 1) * 2];
                const uint32_t* bl_ = &bL[nt >> 1][(nt & 1) * 2];
                mma16816(acc[nt], aH, bh_);
                mma16816(acc[nt], aH, bl_);
                mma16816(acc[nt], aL, bh_);
            }
        }
    }

    __syncthreads();
    #pragma unroll
    for (int nt = 0; nt < 4; nt++) {
        #pragma unroll
        for (int rr = 0; rr < 4; rr++) {
            const int lr  = (lane >> 2) + ((rr >> 1) << 3);
            const int col = nt * 8 + (lane & 3) * 2 + (rr & 1);
            red[wrp * 512 + lr * 32 + col] = acc[nt][rr];
        }
    }
    __syncthreads();

    #pragma unroll
    for (int o = 0; o < 2; o++) {
        const int out = tid + 512 * o;
        const int d = out >> 5, e = out & 31;
        const int hh = d >> 4, lr = d & 15;
        float s = 0.f;
        #pragma unroll
        for (int ww = 0; ww < 8; ww++)
            s += red[(8 * hh + ww) * 512 + lr * 32 + e];
        g_gram_part[(long)chunk * (BATCH*NHEADS*HD*HD) + bh * 1024 + out] = s;
    }

    sq += __shfl_xor_sync(0xffffffffu, sq, 1);
    sq += __shfl_xor_sync(0xffffffffu, sq, 2);
    sq += __shfl_xor_sync(0xffffffffu, sq, 4);
    if (grp == 0) {
        if (ch6 < 32)
            g_qsq_part[chunk * (BATCH*NHEADS*HD) + bh * HD + c] = sq;
        else
            g_ksq_part[chunk * (BATCH*NHEADS*HD) + bh * HD + c] = sq;
    }
}

// ---------------------------------------------------------------------------
// Depthwise conv for v -> SINGLE fp16 in [b][ch][px]. 8 px per thread.
// ---------------------------------------------------------------------------
__global__ __launch_bounds__(256) void dwv(
    const float* __restrict__ qkv, const float* __restrict__ wdw)
{
    const long idx = (long)blockIdx.x * 256 + threadIdx.x;   // < 2*192*8192
    const int px0   = (int)(idx & 8191) << 3;
    const int plane = (int)(idx >> 13);                      // b*192 + ch
    const int ch = plane % KDIM, b = plane / KDIM;
    const int gch = 2 * C_ + ch;

    const float* in = qkv + ((long)b * C3 + gch) * HW_;
    float w[9];
    #pragma unroll
    for (int i = 0; i < 9; i++) w[i] = wdw[gch * 9 + i];

    const int y  = px0 >> 8;
    const int x0 = px0 & 255;
    float o[8];
    conv8(in, w, y, x0, o);

    *reinterpret_cast<uint4*>(g_v_h + (long)plane * HW_ + px0) =
        pack8h(*reinterpret_cast<float4*>(o), *reinterpret_cast<float4*>(o + 4));
}

// convert x (fp32 [b][192][HW]) -> single fp16, same layout. 8 floats/thread.
__global__ __launch_bounds__(256) void split_x(const float* __restrict__ x)
{
    const long idx = (long)blockIdx.x * 256 + threadIdx.x;
    const long off = idx * 8;
    const float4 f0 = *reinterpret_cast<const float4*>(x + off);
    const float4 f1 = *reinterpret_cast<const float4*>(x + off + 4);
    *reinterpret_cast<uint4*>(g_x_h + off) = pack8h(f0, f1);
}

// w_qkv (576x192 fp32) -> A1 fp16 hi/lo (padded 640x192)
__global__ __launch_bounds__(256) void split_w1(const float* __restrict__ w)
{
    const int i = blockIdx.x * 256 + threadIdx.x;
    const float f = w[i];
    const __half h = __float2half_rn(f);
    g_A1_h[i] = h;
    g_A1_l[i] = __float2half_rn(f - __half2float(h));
}

// reduce + normalize + temperature + softmax
__global__ __launch_bounds__(1024) void attn_kernel(const float* __restrict__ temperature)
{
    const int bh = blockIdx.x;
    const int h = bh % NHEADS;
    const int e = threadIdx.x, d = threadIdx.y;

    float g = 0.f, qsq = 0.f, ksq = 0.f;
    #pragma unroll
    for (int ch = 0; ch < GR_CHUNKS; ch++) {
        g   += g_gram_part[(long)ch * (BATCH*NHEADS*HD*HD) + bh * 1024 + d * 32 + e];
        qsq += g_qsq_part[ch * (BATCH*NHEADS*HD) + bh * HD + d];
        ksq += g_ksq_part[ch * (BATCH*NHEADS*HD) + bh * HD + e];
    }
    const float t  = fminf(temperature[h], 5.0f);
    const float qn = fmaxf(sqrtf(qsq), 1e-12f);
    const float kn = fmaxf(sqrtf(ksq), 1e-12f);
    const float val = g / (qn * kn) * t;

    float m = val;
    #pragma unroll
    for (int o = 16; o > 0; o >>= 1) m = fmaxf(m, __shfl_xor_sync(0xffffffffu, m, o));
    const float p = expf(val - m);
    float s = p;
    #pragma unroll
    for (int o = 16; o > 0; o >>= 1) s += __shfl_xor_sync(0xffffffffu, s, o);

    g_attn[bh * 1024 + d * 32 + e] = p / s;
}

// M_eff = w_proj @ blockdiag(attn) -> fp16 hi/lo A2 (padded 256x192/batch)
__global__ __launch_bounds__(256) void meff_kernel(const float* __restrict__ wproj)
{
    const int idx = blockIdx.x * 256 + threadIdx.x;
    const int bz  = blockIdx.y;
    const int o   = idx / C_;
    const int ce  = idx % C_;
    const int h   = ce >> 5, e = ce & 31;

    const float* ar = g_attn + (bz * NHEADS + h) * 1024 + e;
    const float* wr = wproj + o * C_ + h * 32;

    float s = 0.f;
    #pragma unroll
    for (int dd = 0; dd < 32; dd++) s += wr[dd] * ar[dd * 32];

    const __half hi = __float2half_rn(s);
    const long oidx = (long)bz * M2PAD * KDIM + (long)o * KDIM + ce;
    g_A2_h[oidx] = hi;
    g_A2_l[oidx] = __float2half_rn(s - __half2float(hi));
}

// ---------------------------------------------------------------------------
extern "C" void kernel_launch(void* const* d_in, const int* in_sizes, int n_in,
                              void* d_out, int out_size)
{
    (void)in_sizes; (void)n_in; (void)out_size;
    const float* x      = (const float*)d_in[0];
    const float* w_qkv  = (const float*)d_in[1];
    const float* w_dw   = (const float*)d_in[2];
    const float* w_proj = (const float*)d_in[3];
    const float* temp   = (const float*)d_in[4];
    float* out = (float*)d_out;

    float *qkv;
    __half *xh, *vh, *a1h, *a1l, *a2h, *a2l;
    cudaGetSymbolAddress((void**)&qkv, g_qkv);
    cudaGetSymbolAddress((void**)&xh, g_x_h);
    cudaGetSymbolAddress((void**)&vh, g_v_h);
    cudaGetSymbolAddress((void**)&a1h, g_A1_h);
    cudaGetSymbolAddress((void**)&a1l, g_A1_l);
    cudaGetSymbolAddress((void**)&a2h, g_A2_h);
    cudaGetSymbolAddress((void**)&a2l, g_A2_l);

    static bool attr_set = false;
    if (!attr_set) {
        cudaFuncSetAttribute(gemm_ah2, cudaFuncAttributeMaxDynamicSharedMemorySize, GSMEM);
        cudaFuncSetAttribute(dwgram,   cudaFuncAttributeMaxDynamicSharedMemorySize, DG_SMEM);
        attr_set = true;
    }

    // 0) weight + x conversion
    split_w1<<<(M1 * KDIM) / 256, 256>>>(w_qkv);
    split_x<<<(int)(((long)BATCH * KDIM * HW_ / 8) / 256), 256>>>(x);

    // 1) qkv = w_qkv @ x  (A hi/lo, B single fp16)
    gemm_ah2<<<dim3(M1PAD / BM, HW_ / BN, BATCH), 256, GSMEM>>>(
        a1h, a1l, xh, qkv, M1, 0L, (long)C3 * HW_);

    // 2) fused depthwise conv + tensor-core gram partials (q,k)
    dwgram<<<dim3(GR_CHUNKS, BATCH * NHEADS), 512, DG_SMEM>>>(qkv, w_dw);

    // 3) depthwise conv v -> single fp16 [K][N]
    dwv<<<(int)(((long)BATCH * KDIM * HW_ / 8) / 256), 256>>>(qkv, w_dw);

    // 4) softmax + proj-absorb
    attn_kernel<<<BATCH * NHEADS, dim3(32, 32)>>>(temp);
    meff_kernel<<<dim3((C_ * C_) / 256, BATCH), 256>>>(w_proj);

    // 5) out = M_eff @ v  (A hi/lo, B single fp16)
    gemm_ah2<<<dim3(M2PAD / BM, HW_ / BN, BATCH), 256, GSMEM>>>(
        a2h, a2l, vh, out, M2, (long)M2PAD * KDIM, (long)C_ * HW_);
}

// round 15
// speedup vs baseline: 1.0504x; 1.0504x over previous
#include <cuda_runtime.h>
#include <cuda_bf16.h>
#include <cuda_fp16.h>
#include <cstdint>

#define C_     192
#define C3     576
#define NHEADS 6
#define HD     32
#define HH_    256
#define WW_    256
#define HW_    65536
#define BATCH  2
#define KDIM   192
#define M1     576
#define M1PAD  640
#define M2     192
#define M2PAD  256

#define GR_CHUNKS 64           // 64 chunks x 4 rows = 256 image rows
#define ROWS_PC   4

// GEMM tiling (fp16 2-product: single A tile + B hi/lo) — round-13 verified
#define BM 128
#define BN 128
#define BK 32
#define APITCH 80              // bytes per A smem row (64B data + 16B pad)
#define BPITCH 272             // bytes per B smem row (256B data + 16B pad)
#define ATILE (BM * APITCH)    // 10240
#define BTILE (BK * BPITCH)    // 8704
#define BUFSZ (ATILE + 2 * BTILE)      // 27648
#define GSMEM (2 * BUFSZ)              // 55296
#define NITER 6                        // 192/32 k-tiles

// dwgram tiles: 2 fp16 tiles [32ch][256px], pitch 528B (single-product gram)
#define QP_B 528
#define DG_SMEM (2 * 32 * QP_B)        // 33792 B

// ---------------- scratch (device globals) -----------------------------------
__device__ float g_qkv[BATCH * C3 * HW_];
__device__ __half g_x_h[BATCH * KDIM * HW_];          // [b][k][n] fp16 hi
__device__ __half g_x_l[BATCH * KDIM * HW_];          // fp16 lo
__device__ __half g_v_h[BATCH * KDIM * HW_];
__device__ __half g_v_l[BATCH * KDIM * HW_];
__device__ __half g_A1[M1PAD * KDIM];                 // w_qkv fp16 (padded rows zero)
__device__ __half g_A2[BATCH * M2PAD * KDIM];         // M_eff fp16
__device__ float g_gram_part[GR_CHUNKS * BATCH * NHEADS * HD * HD];
__device__ float g_qsq_part [GR_CHUNKS * BATCH * NHEADS * HD];
__device__ float g_ksq_part [GR_CHUNKS * BATCH * NHEADS * HD];
__device__ float g_attn[BATCH * NHEADS * HD * HD];

// ---------------- PTX helpers (sm_80+ only) ----------------------------------
__device__ __forceinline__ uint32_t smem_u32(const void* p) {
    uint32_t a;
    asm("{ .reg .u64 t; cvta.to.shared.u64 t, %1; cvt.u32.u64 %0, t; }" : "=r"(a) : "l"(p));
    return a;
}
#define CP_ASYNC16(dst, src) \
    asm volatile("cp.async.cg.shared.global [%0], [%1], 16;" :: "r"(dst), "l"(src))
#define CP_COMMIT() asm volatile("cp.async.commit_group;" ::: "memory")
#define CP_WAIT(n)  asm volatile("cp.async.wait_group %0;" :: "n"(n) : "memory")

#define LDM_X4(r, addr) \
    asm volatile("ldmatrix.sync.aligned.m8n8.x4.shared.b16 {%0,%1,%2,%3}, [%4];" \
        : "=r"((r)[0]), "=r"((r)[1]), "=r"((r)[2]), "=r"((r)[3]) : "r"(addr))
#define LDM_X2T(r, addr) \
    asm volatile("ldmatrix.sync.aligned.m8n8.x2.trans.shared.b16 {%0,%1}, [%2];" \
        : "=r"((r)[0]), "=r"((r)[1]) : "r"(addr))

// fp16 mma
__device__ __forceinline__ void mma16816h(float* d, const uint32_t* a, const uint32_t* b) {
    asm volatile(
        "mma.sync.aligned.m16n8k16.row.col.f32.f16.f16.f32 "
        "{%0,%1,%2,%3}, {%4,%5,%6,%7}, {%8,%9}, {%0,%1,%2,%3};"
        : "+f"(d[0]), "+f"(d[1]), "+f"(d[2]), "+f"(d[3])
        : "r"(a[0]), "r"(a[1]), "r"(a[2]), "r"(a[3]), "r"(b[0]), "r"(b[1]));
}

// pack 8 fp32 -> 8 fp16 hi (uint4) + 8 fp16 lo (uint4)
__device__ __forceinline__ void split8h(const float4& a, const float4& b, uint4& hi, uint4& lo) {
    float f[8] = {a.x, a.y, a.z, a.w, b.x, b.y, b.z, b.w};
    uint32_t ph[4], pl[4];
    #pragma unroll
    for (int i = 0; i < 4; i++) {
        const __half h0 = __float2half_rn(f[2*i]);
        const __half h1 = __float2half_rn(f[2*i+1]);
        __half2 th = __halves2half2(h0, h1);
        ph[i] = *reinterpret_cast<uint32_t*>(&th);
        __half2 tl = __halves2half2(__float2half_rn(f[2*i]   - __half2float(h0)),
                                    __float2half_rn(f[2*i+1] - __half2float(h1)));
        pl[i] = *reinterpret_cast<uint32_t*>(&tl);
    }
    hi = make_uint4(ph[0], ph[1], ph[2], ph[3]);
    lo = make_uint4(pl[0], pl[1], pl[2], pl[3]);
}

// ---------------------------------------------------------------------------
// fp16 2-product GEMM (round-13 verified): C = A*B.
// A fp16 [M][192]; B fp16 hi/lo [192][HW].  Products: A*Bh + A*Bl.
// ---------------------------------------------------------------------------
__global__ __launch_bounds__(256, 2) void gemm_h2(
    const __half* __restrict__ A,
    const __half* __restrict__ Bh, const __half* __restrict__ Bl,
    float* __restrict__ C, int Mvalid, long aBatch, long cBatch)
{
    extern __shared__ char smem[];
    const uint32_t sb = smem_u32(smem);

    const int tid  = threadIdx.x;
    const int wid  = tid >> 5;
    const int lane = tid & 31;
    const int wm   = wid >> 2;       // 0..1  (64 rows)
    const int wn   = wid & 3;        // 0..3  (32 cols)

    const int bz = blockIdx.z;
    const int m0 = blockIdx.x * BM;
    const int n0 = blockIdx.y * BN;

    A  += (long)bz * aBatch;
    Bh += (long)bz * KDIM * HW_;  Bl += (long)bz * KDIM * HW_;
    C  += (long)bz * cBatch;

    float acc[4][4][4];
    #pragma unroll
    for (int i = 0; i < 4; i++)
        #pragma unroll
        for (int j = 0; j < 4; j++)
            #pragma unroll
            for (int r = 0; r < 4; r++) acc[i][j][r] = 0.f;

    auto loadTiles = [&](int it, int buf) {
        const int k0 = it * BK;
        const uint32_t base = sb + (uint32_t)buf * BUFSZ;
        #pragma unroll
        for (int i = 0; i < 2; i++) {
            const int ca = tid + 256 * i;          // 0..511
            const int ar = ca >> 2, as_ = ca & 3;
            CP_ASYNC16(base + ar * APITCH + as_ * 16,
                       A + (long)(m0 + ar) * KDIM + k0 + as_ * 8);
            const int br = ca >> 4, bs_ = ca & 15;
            const long gob = (long)(k0 + br) * HW_ + n0 + bs_ * 8;
            const uint32_t sofb = br * BPITCH + bs_ * 16;
            CP_ASYNC16(base + ATILE + sofb,         Bh + gob);
            CP_ASYNC16(base + ATILE + BTILE + sofb, Bl + gob);
        }
    };

    loadTiles(0, 0);
    CP_COMMIT();

    #pragma unroll 1
    for (int it = 0; it < NITER; it++) {
        if (it + 1 < NITER) {
            loadTiles(it + 1, (it + 1) & 1);
            CP_COMMIT();
            CP_WAIT(1);
        } else {
            CP_WAIT(0);
        }
        __syncthreads();

        const uint32_t base = sb + (uint32_t)(it & 1) * BUFSZ;
        const uint32_t aB  = base;
        const uint32_t bHb = base + ATILE, bLb = bHb + BTILE;

        #pragma unroll
        for (int kf = 0; kf < 2; kf++) {
            uint32_t a[4][4], bH[4][2], bL[4][2];
            #pragma unroll
            for (int i = 0; i < 4; i++) {
                const uint32_t ro = (uint32_t)(wm * 64 + i * 16 + (lane & 15)) * APITCH
                                  + kf * 32 + ((lane >> 4) << 4);
                LDM_X4(a[i], aB + ro);
            }
            #pragma unroll
            for (int j = 0; j < 4; j++) {
                const uint32_t ro = (uint32_t)(kf * 16 + (lane & 15)) * BPITCH
                                  + (uint32_t)(wn * 32 + j * 8) * 2;
                LDM_X2T(bH[j], bHb + ro);
                LDM_X2T(bL[j], bLb + ro);
            }
            #pragma unroll
            for (int i = 0; i < 4; i++)
                #pragma unroll
                for (int j = 0; j < 4; j++) {
                    mma16816h(acc[i][j], a[i], bH[j]);
                    mma16816h(acc[i][j], a[i], bL[j]);
                }
        }
        __syncthreads();
    }

    const int rw = m0 + wm * 64 + (lane >> 2);
    const int cw = n0 + wn * 32 + (lane & 3) * 2;
    #pragma unroll
    for (int i = 0; i < 4; i++) {
        #pragma unroll
        for (int j = 0; j < 4; j++) {
            const int row = rw + i * 16;
            const int col = cw + j * 8;
            if (row < Mvalid)
                *reinterpret_cast<float2*>(C + (long)row * HW_ + col) =
                    make_float2(acc[i][j][0], acc[i][j][1]);
            if (row + 8 < Mvalid)
                *reinterpret_cast<float2*>(C + (long)(row + 8) * HW_ + col) =
                    make_float2(acc[i][j][2], acc[i][j][3]);
        }
    }
}

// ---------------------------------------------------------------------------
// 4-pixel depthwise conv: rows y-1..y+1, x0..x0+3 (x0 % 4 == 0)
// ---------------------------------------------------------------------------
__device__ __forceinline__ void conv4(
    const float* __restrict__ plane, const float* __restrict__ w,
    int y, int x0, float out[4])
{
    out[0] = out[1] = out[2] = out[3] = 0.f;
    #pragma unroll
    for (int dy = -1; dy <= 1; dy++) {
        const int yy = y + dy;
        if (yy < 0 || yy >= HH_) continue;
        const float* row = plane + yy * WW_ + x0;
        const float4 m = *reinterpret_cast<const float4*>(row);
        const float lft = (x0 > 0)       ? row[-1] : 0.f;
        const float rgt = (x0 + 4 < 256) ? row[4]  : 0.f;
        const float w0 = w[(dy + 1) * 3 + 0];
        const float w1 = w[(dy + 1) * 3 + 1];
        const float w2 = w[(dy + 1) * 3 + 2];
        out[0] += w0 * lft + w1 * m.x + w2 * m.y;
        out[1] += w0 * m.x + w1 * m.y + w2 * m.z;
        out[2] += w0 * m.y + w1 * m.z + w2 * m.w;
        out[3] += w0 * m.z + w1 * m.w + w2 * rgt;
    }
}

// ---------------------------------------------------------------------------
// 8-pixel depthwise conv (used by dwv: consecutive threads = consecutive spans)
// ---------------------------------------------------------------------------
__device__ __forceinline__ void conv8(
    const float* __restrict__ plane, const float* __restrict__ w,
    int y, int x0, float out[8])
{
    #pragma unroll
    for (int i = 0; i < 8; i++) out[i] = 0.f;
    #pragma unroll
    for (int dy = -1; dy <= 1; dy++) {
        const int yy = y + dy;
        if (yy < 0 || yy >= HH_) continue;
        const float* row = plane + yy * WW_ + x0;
        const float4 a = *reinterpret_cast<const float4*>(row);
        const float4 b = *reinterpret_cast<const float4*>(row + 4);
        const float lft = (x0 > 0)       ? row[-1] : 0.f;
        const float rgt = (x0 + 8 < 256) ? row[8]  : 0.f;
        const float w0 = w[(dy + 1) * 3 + 0];
        const float w1 = w[(dy + 1) * 3 + 1];
        const float w2 = w[(dy + 1) * 3 + 2];
        out[0] += w0 * lft + w1 * a.x + w2 * a.y;
        out[1] += w0 * a.x + w1 * a.y + w2 * a.z;
        out[2] += w0 * a.y + w1 * a.z + w2 * a.w;
        out[3] += w0 * a.z + w1 * a.w + w2 * b.x;
        out[4] += w0 * a.w + w1 * b.x + w2 * b.y;
        out[5] += w0 * b.x + w1 * b.y + w2 * b.z;
        out[6] += w0 * b.y + w1 * b.z + w2 * b.w;
        out[7] += w0 * b.z + w1 * b.w + w2 * rgt;
    }
}

// ---------------------------------------------------------------------------
// Fused depthwise conv (q,k) + SINGLE-fp16 tensor-core Gram partials.
// Logit error from fp16 gram is ~1e-6 absolute (normalized by qn*kn=65536).
// Sum-squares remain exact fp32 from conv registers.
// ---------------------------------------------------------------------------
__global__ __launch_bounds__(512, 2) void dwgram(
    const float* __restrict__ qkv, const float* __restrict__ wdw)
{
    extern __shared__ char smraw[];
    const uint32_t sb = smem_u32(smraw);
    const uint32_t qhb = sb;
    const uint32_t khb = sb + 32 * QP_B;
    float* red = reinterpret_cast<float*>(smraw);   // reused after last mma

    const int bh = blockIdx.y;
    const int b = bh / NHEADS, h = bh % NHEADS;
    const int chunk = blockIdx.x;
    const int tid = threadIdx.x;
    const int lane = tid & 31;

    // conv mapping: 64 channels x 8 x-groups (interleaved 4-px tasks)
    const int ch6 = tid >> 3;
    const int grp = tid & 7;
    const int c   = ch6 & 31;
    const int gch = (ch6 < 32) ? (h * HD + c) : (C_ + h * HD + c);
    const float* plane = qkv + ((long)b * C3 + gch) * HW_;
    float w[9];
    #pragma unroll
    for (int i = 0; i < 9; i++) w[i] = wdw[gch * 9 + i];
    const uint32_t dHo = (ch6 < 32 ? 0u : 32u * QP_B) + (uint32_t)c * QP_B;

    // gram warp mapping
    const int wrp  = tid >> 5;
    const int half = wrp >> 3;
    const int slc  = wrp & 7;

    float acc[4][4];
    #pragma unroll
    for (int j = 0; j < 4; j++)
        #pragma unroll
        for (int r = 0; r < 4; r++) acc[j][r] = 0.f;
    float sq = 0.f;

    #pragma unroll 1
    for (int r = 0; r < ROWS_PC; r++) {
        const int y = chunk * ROWS_PC + r;
        __syncthreads();
        #pragma unroll
        for (int i = 0; i < 8; i++) {
            const int x0 = (grp + 8 * i) * 4;
            float o[4];
            conv4(plane, w, y, x0, o);
            sq += o[0]*o[0] + o[1]*o[1] + o[2]*o[2] + o[3]*o[3];
            __half2 t0 = __halves2half2(__float2half_rn(o[0]), __float2half_rn(o[1]));
            __half2 t1 = __halves2half2(__float2half_rn(o[2]), __float2half_rn(o[3]));
            uint2 ph;
            ph.x = *reinterpret_cast<uint32_t*>(&t0);
            ph.y = *reinterpret_cast<uint32_t*>(&t1);
            *reinterpret_cast<uint2*>(smraw + dHo + x0 * 2) = ph;
        }
        __syncthreads();

        // gram mma over this row's 256 px: warp handles 32-px slice
        #pragma unroll
        for (int c2 = 0; c2 < 2; c2++) {
            const uint32_t off = (uint32_t)(slc * 64 + c2 * 32);
            uint32_t aH[4], bH[2][4];
            const uint32_t ra = (uint32_t)(16 * half + (lane & 15)) * QP_B
                              + ((lane >> 4) << 4) + off;
            LDM_X4(aH, qhb + ra);
            #pragma unroll
            for (int nt2 = 0; nt2 < 2; nt2++) {
                const uint32_t rb = (uint32_t)((lane & 7) + ((lane >> 4) << 3) + 16 * nt2) * QP_B
                                  + (((lane >> 3) & 1) << 4) + off;
                LDM_X4(bH[nt2], khb + rb);
            }
            #pragma unroll
            for (int nt = 0; nt < 4; nt++)
                mma16816h(acc[nt], aH, &bH[nt >> 1][(nt & 1) * 2]);
        }
    }

    // reduce 16 warp-partials -> 32x32
    __syncthreads();
    #pragma unroll
    for (int nt = 0; nt < 4; nt++) {
        #pragma unroll
        for (int rr = 0; rr < 4; rr++) {
            const int lr  = (lane >> 2) + ((rr >> 1) << 3);
            const int col = nt * 8 + (lane & 3) * 2 + (rr & 1);
            red[wrp * 512 + lr * 32 + col] = acc[nt][rr];
        }
    }
    __syncthreads();

    #pragma unroll
    for (int o = 0; o < 2; o++) {
        const int out = tid + 512 * o;
        const int d = out >> 5, e = out & 31;
        const int hh = d >> 4, lr = d & 15;
        float s = 0.f;
        #pragma unroll
        for (int ww = 0; ww < 8; ww++)
            s += red[(8 * hh + ww) * 512 + lr * 32 + e];
        g_gram_part[(long)chunk * (BATCH*NHEADS*HD*HD) + bh * 1024 + out] = s;
    }

    sq += __shfl_xor_sync(0xffffffffu, sq, 1);
    sq += __shfl_xor_sync(0xffffffffu, sq, 2);
    sq += __shfl_xor_sync(0xffffffffu, sq, 4);
    if (grp == 0) {
        if (ch6 < 32)
            g_qsq_part[chunk * (BATCH*NHEADS*HD) + bh * HD + c] = sq;
        else
            g_ksq_part[chunk * (BATCH*NHEADS*HD) + bh * HD + c] = sq;
    }
}

// ---------------------------------------------------------------------------
// Depthwise conv for v -> split fp16 hi/lo in [b][ch][px]. 8 px per thread.
// ---------------------------------------------------------------------------
__global__ __launch_bounds__(256) void dwv(
    const float* __restrict__ qkv, const float* __restrict__ wdw)
{
    const long idx = (long)blockIdx.x * 256 + threadIdx.x;   // < 2*192*8192
    const int px0   = (int)(idx & 8191) << 3;
    const int plane = (int)(idx >> 13);                      // b*192 + ch
    const int ch = plane % KDIM, b = plane / KDIM;
    const int gch = 2 * C_ + ch;

    const float* in = qkv + ((long)b * C3 + gch) * HW_;
    float w[9];
    #pragma unroll
    for (int i = 0; i < 9; i++) w[i] = wdw[gch * 9 + i];

    const int y  = px0 >> 8;
    const int x0 = px0 & 255;
    float o[8];
    conv8(in, w, y, x0, o);

    uint4 hi, lo;
    split8h(*reinterpret_cast<float4*>(o), *reinterpret_cast<float4*>(o + 4), hi, lo);
    const long off = (long)plane * HW_ + px0;
    *reinterpret_cast<uint4*>(g_v_h + off) = hi;
    *reinterpret_cast<uint4*>(g_v_l + off) = lo;
}

// split x (fp32 [b][192][HW]) -> fp16 hi/lo, same layout. 8 floats/thread.
__global__ __launch_bounds__(256) void split_x(const float* __restrict__ x)
{
    const long idx = (long)blockIdx.x * 256 + threadIdx.x;
    const long off = idx * 8;
    const float4 f0 = *reinterpret_cast<const float4*>(x + off);
    const float4 f1 = *reinterpret_cast<const float4*>(x + off + 4);
    uint4 hi, lo;
    split8h(f0, f1, hi, lo);
    *reinterpret_cast<uint4*>(g_x_h + off) = hi;
    *reinterpret_cast<uint4*>(g_x_l + off) = lo;
}

// w_qkv (576x192 fp32) -> A1 fp16 (padded 640x192)
__global__ __launch_bounds__(256) void split_w1(const float* __restrict__ w)
{
    const int i = blockIdx.x * 256 + threadIdx.x;
    g_A1[i] = __float2half_rn(w[i]);
}

// reduce + normalize + temperature + softmax
__global__ __launch_bounds__(1024) void attn_kernel(const float* __restrict__ temperature)
{
    const int bh = blockIdx.x;
    const int h = bh % NHEADS;
    const int e = threadIdx.x, d = threadIdx.y;

    float g = 0.f, qsq = 0.f, ksq = 0.f;
    #pragma unroll
    for (int ch = 0; ch < GR_CHUNKS; ch++) {
        g   += g_gram_part[(long)ch * (BATCH*NHEADS*HD*HD) + bh * 1024 + d * 32 + e];
        qsq += g_qsq_part[ch * (BATCH*NHEADS*HD) + bh * HD + d];
        ksq += g_ksq_part[ch * (BATCH*NHEADS*HD) + bh * HD + e];
    }
    const float t  = fminf(temperature[h], 5.0f);
    const float qn = fmaxf(sqrtf(qsq), 1e-12f);
    const float kn = fmaxf(sqrtf(ksq), 1e-12f);
    const float val = g / (qn * kn) * t;

    float m = val;
    #pragma unroll
    for (int o = 16; o > 0; o >>= 1) m = fmaxf(m, __shfl_xor_sync(0xffffffffu, m, o));
    const float p = expf(val - m);
    float s = p;
    #pragma unroll
    for (int o = 16; o > 0; o >>= 1) s += __shfl_xor_sync(0xffffffffu, s, o);

    g_attn[bh * 1024 + d * 32 + e] = p / s;
}

// M_eff = w_proj @ blockdiag(attn) -> fp16 A2 (padded 256x192/batch)
__global__ __launch_bounds__(256) void meff_kernel(const float* __restrict__ wproj)
{
    const int idx = blockIdx.x * 256 + threadIdx.x;
    const int bz  = blockIdx.y;
    const int o   = idx / C_;
    const int ce  = idx % C_;
    const int h   = ce >> 5, e = ce & 31;

    const float* ar = g_attn + (bz * NHEADS + h) * 1024 + e;
    const float* wr = wproj + o * C_ + h * 32;

    float s = 0.f;
    #pragma unroll
    for (int dd = 0; dd < 32; dd++) s += wr[dd] * ar[dd * 32];

    g_A2[(long)bz * M2PAD * KDIM + (long)o * KDIM + ce] = __float2half_rn(s);
}

// ---------------------------------------------------------------------------
extern "C" void kernel_launch(void* const* d_in, const int* in_sizes, int n_in,
                              void* d_out, int out_size)
{
    (void)in_sizes; (void)n_in; (void)out_size;
    const float* x      = (const float*)d_in[0];
    const float* w_qkv  = (const float*)d_in[1];
    const float* w_dw   = (const float*)d_in[2];
    const float* w_proj = (const float*)d_in[3];
    const float* temp   = (const float*)d_in[4];
    float* out = (float*)d_out;

    float *qkv;
    __half *xh, *xl, *vh, *vl, *a1, *a2;
    cudaGetSymbolAddress((void**)&qkv, g_qkv);
    cudaGetSymbolAddress((void**)&xh, g_x_h);
    cudaGetSymbolAddress((void**)&xl, g_x_l);
    cudaGetSymbolAddress((void**)&vh, g_v_h);
    cudaGetSymbolAddress((void**)&vl, g_v_l);
    cudaGetSymbolAddress((void**)&a1, g_A1);
    cudaGetSymbolAddress((void**)&a2, g_A2);

    static bool attr_set = false;
    if (!attr_set) {
        cudaFuncSetAttribute(gemm_h2, cudaFuncAttributeMaxDynamicSharedMemorySize, GSMEM);
        cudaFuncSetAttribute(dwgram,  cudaFuncAttributeMaxDynamicSharedMemorySize, DG_SMEM);
        attr_set = true;
    }

    // 0) weight + x conversion
    split_w1<<<(M1 * KDIM) / 256, 256>>>(w_qkv);
    split_x<<<(int)(((long)BATCH * KDIM * HW_ / 8) / 256), 256>>>(x);

    // 1) qkv = w_qkv @ x  (fp16 2-product, B hi/lo)
    gemm_h2<<<dim3(M1PAD / BM, HW_ / BN, BATCH), 256, GSMEM>>>(
        a1, xh, xl, qkv, M1, 0L, (long)C3 * HW_);

    // 2) fused depthwise conv + single-fp16 tensor-core gram partials (q,k)
    dwgram<<<dim3(GR_CHUNKS, BATCH * NHEADS), 512, DG_SMEM>>>(qkv, w_dw);

    // 3) depthwise conv v -> split fp16 [K][N]
    dwv<<<(int)(((long)BATCH * KDIM * HW_ / 8) / 256), 256>>>(qkv, w_dw);

    // 4) softmax + proj-absorb
    attn_kernel<<<BATCH * NHEADS, dim3(32, 32)>>>(temp);
    meff_kernel<<<dim3((C_ * C_) / 256, BATCH), 256>>>(w_proj);

    // 5) out = M_eff @ v  (fp16 2-product, B hi/lo)
    gemm_h2<<<dim3(M2PAD / BM, HW_ / BN, BATCH), 256, GSMEM>>>(
        a2, vh, vl, out, M2, (long)M2PAD * KDIM, (long)C_ * HW_);
}

// round 16
// speedup vs baseline: 1.1100x; 1.0567x over previous
#include <cuda_runtime.h>
#include <cuda_bf16.h>
#include <cuda_fp16.h>
#include <cstdint>

#define C_     192
#define C3     576
#define NHEADS 6
#define HD     32
#define HH_    256
#define WW_    256
#define HW_    65536
#define BATCH  2
#define KDIM   192
#define M1     576
#define M1PAD  640
#define M2     192
#define M2PAD  256

#define GR_CHUNKS 64           // 64 chunks x 4 rows = 256 image rows
#define ROWS_PC   4

// GEMM tiling (fp16 2-product: single A tile + B hi/lo)
#define BM 128
#define BN 128
#define BK 32
#define APITCH 80              // bytes per A smem row (64B data + 16B pad)
#define BPITCH 272             // bytes per B smem row (256B data + 16B pad)
#define ATILE (BM * APITCH)    // 10240
#define BTILE (BK * BPITCH)    // 8704
#define BUFSZ (ATILE + 2 * BTILE)      // 27648
#define GSMEM (2 * BUFSZ)              // 55296
#define NITER 6                        // 192/32 k-tiles

// dwgram tiles: 2 fp16 tiles [32ch][256px], pitch 528B (single-product gram)
#define QP_B 528
#define DG_SMEM (2 * 32 * QP_B)        // 33792 B

// ---------------- scratch (device globals) -----------------------------------
__device__ __half g_qkv_h[BATCH * C3 * HW_];          // qkv intermediate, fp16
__device__ __half g_x_h[BATCH * KDIM * HW_];          // [b][k][n] fp16 hi
__device__ __half g_x_l[BATCH * KDIM * HW_];          // fp16 lo
__device__ __half g_v_h[BATCH * KDIM * HW_];
__device__ __half g_v_l[BATCH * KDIM * HW_];
__device__ __half g_A1[M1PAD * KDIM];                 // w_qkv fp16 (padded rows zero)
__device__ __half g_A2[BATCH * M2PAD * KDIM];         // M_eff fp16
__device__ float g_gram_part[GR_CHUNKS * BATCH * NHEADS * HD * HD];
__device__ float g_qsq_part [GR_CHUNKS * BATCH * NHEADS * HD];
__device__ float g_ksq_part [GR_CHUNKS * BATCH * NHEADS * HD];
__device__ float g_attn[BATCH * NHEADS * HD * HD];

// ---------------- PTX helpers (sm_80+ only) ----------------------------------
__device__ __forceinline__ uint32_t smem_u32(const void* p) {
    uint32_t a;
    asm("{ .reg .u64 t; cvta.to.shared.u64 t, %1; cvt.u32.u64 %0, t; }" : "=r"(a) : "l"(p));
    return a;
}
#define CP_ASYNC16(dst, src) \
    asm volatile("cp.async.cg.shared.global [%0], [%1], 16;" :: "r"(dst), "l"(src))
#define CP_COMMIT() asm volatile("cp.async.commit_group;" ::: "memory")
#define CP_WAIT(n)  asm volatile("cp.async.wait_group %0;" :: "n"(n) : "memory")

#define LDM_X4(r, addr) \
    asm volatile("ldmatrix.sync.aligned.m8n8.x4.shared.b16 {%0,%1,%2,%3}, [%4];" \
        : "=r"((r)[0]), "=r"((r)[1]), "=r"((r)[2]), "=r"((r)[3]) : "r"(addr))
#define LDM_X2T(r, addr) \
    asm volatile("ldmatrix.sync.aligned.m8n8.x2.trans.shared.b16 {%0,%1}, [%2];" \
        : "=r"((r)[0]), "=r"((r)[1]) : "r"(addr))

// fp16 mma
__device__ __forceinline__ void mma16816h(float* d, const uint32_t* a, const uint32_t* b) {
    asm volatile(
        "mma.sync.aligned.m16n8k16.row.col.f32.f16.f16.f32 "
        "{%0,%1,%2,%3}, {%4,%5,%6,%7}, {%8,%9}, {%0,%1,%2,%3};"
        : "+f"(d[0]), "+f"(d[1]), "+f"(d[2]), "+f"(d[3])
        : "r"(a[0]), "r"(a[1]), "r"(a[2]), "r"(a[3]), "r"(b[0]), "r"(b[1]));
}

// pack 8 fp32 -> 8 fp16 hi (uint4) + 8 fp16 lo (uint4)
__device__ __forceinline__ void split8h(const float4& a, const float4& b, uint4& hi, uint4& lo) {
    float f[8] = {a.x, a.y, a.z, a.w, b.x, b.y, b.z, b.w};
    uint32_t ph[4], pl[4];
    #pragma unroll
    for (int i = 0; i < 4; i++) {
        const __half h0 = __float2half_rn(f[2*i]);
        const __half h1 = __float2half_rn(f[2*i+1]);
        __half2 th = __halves2half2(h0, h1);
        ph[i] = *reinterpret_cast<uint32_t*>(&th);
        __half2 tl = __halves2half2(__float2half_rn(f[2*i]   - __half2float(h0)),
                                    __float2half_rn(f[2*i+1] - __half2float(h1)));
        pl[i] = *reinterpret_cast<uint32_t*>(&tl);
    }
    hi = make_uint4(ph[0], ph[1], ph[2], ph[3]);
    lo = make_uint4(pl[0], pl[1], pl[2], pl[3]);
}

// ---------------------------------------------------------------------------
// fp16 2-product GEMM: C = A*B.  A fp16 [M][192]; B fp16 hi/lo [192][HW].
// HALF_OUT: write fp16 (qkv intermediate) vs fp32 (final output).
// ---------------------------------------------------------------------------
template <bool HALF_OUT>
__global__ __launch_bounds__(256, 2) void gemm_h2(
    const __half* __restrict__ A,
    const __half* __restrict__ Bh, const __half* __restrict__ Bl,
    void* __restrict__ Cv, int Mvalid, long aBatch, long cBatch)
{
    extern __shared__ char smem[];
    const uint32_t sb = smem_u32(smem);

    const int tid  = threadIdx.x;
    const int wid  = tid >> 5;
    const int lane = tid & 31;
    const int wm   = wid >> 2;       // 0..1  (64 rows)
    const int wn   = wid & 3;        // 0..3  (32 cols)

    const int bz = blockIdx.z;
    const int m0 = blockIdx.x * BM;
    const int n0 = blockIdx.y * BN;

    A  += (long)bz * aBatch;
    Bh += (long)bz * KDIM * HW_;  Bl += (long)bz * KDIM * HW_;

    float acc[4][4][4];
    #pragma unroll
    for (int i = 0; i < 4; i++)
        #pragma unroll
        for (int j = 0; j < 4; j++)
            #pragma unroll
            for (int r = 0; r < 4; r++) acc[i][j][r] = 0.f;

    auto loadTiles = [&](int it, int buf) {
        const int k0 = it * BK;
        const uint32_t base = sb + (uint32_t)buf * BUFSZ;
        #pragma unroll
        for (int i = 0; i < 2; i++) {
            const int ca = tid + 256 * i;          // 0..511
            const int ar = ca >> 2, as_ = ca & 3;
            CP_ASYNC16(base + ar * APITCH + as_ * 16,
                       A + (long)(m0 + ar) * KDIM + k0 + as_ * 8);
            const int br = ca >> 4, bs_ = ca & 15;
            const long gob = (long)(k0 + br) * HW_ + n0 + bs_ * 8;
            const uint32_t sofb = br * BPITCH + bs_ * 16;
            CP_ASYNC16(base + ATILE + sofb,         Bh + gob);
            CP_ASYNC16(base + ATILE + BTILE + sofb, Bl + gob);
        }
    };

    loadTiles(0, 0);
    CP_COMMIT();

    #pragma unroll 1
    for (int it = 0; it < NITER; it++) {
        if (it + 1 < NITER) {
            loadTiles(it + 1, (it + 1) & 1);
            CP_COMMIT();
            CP_WAIT(1);
        } else {
            CP_WAIT(0);
        }
        __syncthreads();

        const uint32_t base = sb + (uint32_t)(it & 1) * BUFSZ;
        const uint32_t aB  = base;
        const uint32_t bHb = base + ATILE, bLb = bHb + BTILE;

        #pragma unroll
        for (int kf = 0; kf < 2; kf++) {
            uint32_t a[4][4], bH[4][2], bL[4][2];
            #pragma unroll
            for (int i = 0; i < 4; i++) {
                const uint32_t ro = (uint32_t)(wm * 64 + i * 16 + (lane & 15)) * APITCH
                                  + kf * 32 + ((lane >> 4) << 4);
                LDM_X4(a[i], aB + ro);
            }
            #pragma unroll
            for (int j = 0; j < 4; j++) {
                const uint32_t ro = (uint32_t)(kf * 16 + (lane & 15)) * BPITCH
                                  + (uint32_t)(wn * 32 + j * 8) * 2;
                LDM_X2T(bH[j], bHb + ro);
                LDM_X2T(bL[j], bLb + ro);
            }
            #pragma unroll
            for (int i = 0; i < 4; i++)
                #pragma unroll
                for (int j = 0; j < 4; j++) {
                    mma16816h(acc[i][j], a[i], bH[j]);
                    mma16816h(acc[i][j], a[i], bL[j]);
                }
        }
        __syncthreads();
    }

    const int rw = m0 + wm * 64 + (lane >> 2);
    const int cw = n0 + wn * 32 + (lane & 3) * 2;
    if (HALF_OUT) {
        __half* C = reinterpret_cast<__half*>(Cv) + (long)bz * cBatch;
        #pragma unroll
        for (int i = 0; i < 4; i++) {
            #pragma unroll
            for (int j = 0; j < 4; j++) {
                const int row = rw + i * 16;
                const int col = cw + j * 8;
                if (row < Mvalid)
                    *reinterpret_cast<__half2*>(C + (long)row * HW_ + col) =
                        __halves2half2(__float2half_rn(acc[i][j][0]),
                                       __float2half_rn(acc[i][j][1]));
                if (row + 8 < Mvalid)
                    *reinterpret_cast<__half2*>(C + (long)(row + 8) * HW_ + col) =
                        __halves2half2(__float2half_rn(acc[i][j][2]),
                                       __float2half_rn(acc[i][j][3]));
            }
        }
    } else {
        float* C = reinterpret_cast<float*>(Cv) + (long)bz * cBatch;
        #pragma unroll
        for (int i = 0; i < 4; i++) {
            #pragma unroll
            for (int j = 0; j < 4; j++) {
                const int row = rw + i * 16;
                const int col = cw + j * 8;
                if (row < Mvalid)
                    *reinterpret_cast<float2*>(C + (long)row * HW_ + col) =
                        make_float2(acc[i][j][0], acc[i][j][1]);
                if (row + 8 < Mvalid)
                    *reinterpret_cast<float2*>(C + (long)(row + 8) * HW_ + col) =
                        make_float2(acc[i][j][2], acc[i][j][3]);
            }
        }
    }
}

// ---------------------------------------------------------------------------
// 4-pixel depthwise conv over fp16 plane: rows y-1..y+1, x0 % 4 == 0
// ---------------------------------------------------------------------------
__device__ __forceinline__ void conv4h(
    const __half* __restrict__ plane, const float* __restrict__ w,
    int y, int x0, float out[4])
{
    out[0] = out[1] = out[2] = out[3] = 0.f;
    #pragma unroll
    for (int dy = -1; dy <= 1; dy++) {
        const int yy = y + dy;
        if (yy < 0 || yy >= HH_) continue;
        const __half* row = plane + yy * WW_ + x0;
        const uint2 u = *reinterpret_cast<const uint2*>(row);   // 8B aligned
        const __half2 h01 = *reinterpret_cast<const __half2*>(&u.x);
        const __half2 h23 = *reinterpret_cast<const __half2*>(&u.y);
        const float m0 = __low2float(h01), m1 = __high2float(h01);
        const float m2 = __low2float(h23), m3 = __high2float(h23);
        const float lft = (x0 > 0)       ? __half2float(row[-1]) : 0.f;
        const float rgt = (x0 + 4 < 256) ? __half2float(row[4])  : 0.f;
        const float w0 = w[(dy + 1) * 3 + 0];
        const float w1 = w[(dy + 1) * 3 + 1];
        const float w2 = w[(dy + 1) * 3 + 2];
        out[0] += w0 * lft + w1 * m0 + w2 * m1;
        out[1] += w0 * m0  + w1 * m1 + w2 * m2;
        out[2] += w0 * m1  + w1 * m2 + w2 * m3;
        out[3] += w0 * m2  + w1 * m3 + w2 * rgt;
    }
}

// ---------------------------------------------------------------------------
// 8-pixel depthwise conv over fp16 plane (dwv; x0 % 8 == 0 -> 16B aligned)
// ---------------------------------------------------------------------------
__device__ __forceinline__ void conv8h(
    const __half* __restrict__ plane, const float* __restrict__ w,
    int y, int x0, float out[8])
{
    #pragma unroll
    for (int i = 0; i < 8; i++) out[i] = 0.f;
    #pragma unroll
    for (int dy = -1; dy <= 1; dy++) {
        const int yy = y + dy;
        if (yy < 0 || yy >= HH_) continue;
        const __half* row = plane + yy * WW_ + x0;
        const uint4 u = *reinterpret_cast<const uint4*>(row);
        const __half2 p0 = *reinterpret_cast<const __half2*>(&u.x);
        const __half2 p1 = *reinterpret_cast<const __half2*>(&u.y);
        const __half2 p2 = *reinterpret_cast<const __half2*>(&u.z);
        const __half2 p3 = *reinterpret_cast<const __half2*>(&u.w);
        float m[8] = {__low2float(p0), __high2float(p0), __low2float(p1), __high2float(p1),
                      __low2float(p2), __high2float(p2), __low2float(p3), __high2float(p3)};
        const float lft = (x0 > 0)       ? __half2float(row[-1]) : 0.f;
        const float rgt = (x0 + 8 < 256) ? __half2float(row[8])  : 0.f;
        const float w0 = w[(dy + 1) * 3 + 0];
        const float w1 = w[(dy + 1) * 3 + 1];
        const float w2 = w[(dy + 1) * 3 + 2];
        out[0] += w0 * lft  + w1 * m[0] + w2 * m[1];
        #pragma unroll
        for (int i = 1; i < 7; i++)
            out[i] += w0 * m[i-1] + w1 * m[i] + w2 * m[i+1];
        out[7] += w0 * m[6] + w1 * m[7] + w2 * rgt;
    }
}

// ---------------------------------------------------------------------------
// Fused depthwise conv (q,k) + single-fp16 tensor-core Gram partials.
// ---------------------------------------------------------------------------
__global__ __launch_bounds__(512, 2) void dwgram(
    const __half* __restrict__ qkv, const float* __restrict__ wdw)
{
    extern __shared__ char smraw[];
    const uint32_t sb = smem_u32(smraw);
    const uint32_t qhb = sb;
    const uint32_t khb = sb + 32 * QP_B;
    float* red = reinterpret_cast<float*>(smraw);   // reused after last mma

    const int bh = blockIdx.y;
    const int b = bh / NHEADS, h = bh % NHEADS;
    const int chunk = blockIdx.x;
    const int tid = threadIdx.x;
    const int lane = tid & 31;

    // conv mapping: 64 channels x 8 x-groups (interleaved 4-px tasks)
    const int ch6 = tid >> 3;
    const int grp = tid & 7;
    const int c   = ch6 & 31;
    const int gch = (ch6 < 32) ? (h * HD + c) : (C_ + h * HD + c);
    const __half* plane = qkv + ((long)b * C3 + gch) * HW_;
    float w[9];
    #pragma unroll
    for (int i = 0; i < 9; i++) w[i] = wdw[gch * 9 + i];
    const uint32_t dHo = (ch6 < 32 ? 0u : 32u * QP_B) + (uint32_t)c * QP_B;

    // gram warp mapping
    const int wrp  = tid >> 5;
    const int half = wrp >> 3;
    const int slc  = wrp & 7;

    float acc[4][4];
    #pragma unroll
    for (int j = 0; j < 4; j++)
        #pragma unroll
        for (int r = 0; r < 4; r++) acc[j][r] = 0.f;
    float sq = 0.f;

    #pragma unroll 1
    for (int r = 0; r < ROWS_PC; r++) {
        const int y = chunk * ROWS_PC + r;
        __syncthreads();
        #pragma unroll
        for (int i = 0; i < 8; i++) {
            const int x0 = (grp + 8 * i) * 4;
            float o[4];
            conv4h(plane, w, y, x0, o);
            sq += o[0]*o[0] + o[1]*o[1] + o[2]*o[2] + o[3]*o[3];
            __half2 t0 = __halves2half2(__float2half_rn(o[0]), __float2half_rn(o[1]));
            __half2 t1 = __halves2half2(__float2half_rn(o[2]), __float2half_rn(o[3]));
            uint2 ph;
            ph.x = *reinterpret_cast<uint32_t*>(&t0);
            ph.y = *reinterpret_cast<uint32_t*>(&t1);
            *reinterpret_cast<uint2*>(smraw + dHo + x0 * 2) = ph;
        }
        __syncthreads();

        // gram mma over this row's 256 px: warp handles 32-px slice
        #pragma unroll
        for (int c2 = 0; c2 < 2; c2++) {
            const uint32_t off = (uint32_t)(slc * 64 + c2 * 32);
            uint32_t aH[4], bH[2][4];
            const uint32_t ra = (uint32_t)(16 * half + (lane & 15)) * QP_B
                              + ((lane >> 4) << 4) + off;
            LDM_X4(aH, qhb + ra);
            #pragma unroll
            for (int nt2 = 0; nt2 < 2; nt2++) {
                const uint32_t rb = (uint32_t)((lane & 7) + ((lane >> 4) << 3) + 16 * nt2) * QP_B
                                  + (((lane >> 3) & 1) << 4) + off;
                LDM_X4(bH[nt2], khb + rb);
            }
            #pragma unroll
            for (int nt = 0; nt < 4; nt++)
                mma16816h(acc[nt], aH, &bH[nt >> 1][(nt & 1) * 2]);
        }
    }

    // reduce 16 warp-partials -> 32x32
    __syncthreads();
    #pragma unroll
    for (int nt = 0; nt < 4; nt++) {
        #pragma unroll
        for (int rr = 0; rr < 4; rr++) {
            const int lr  = (lane >> 2) + ((rr >> 1) << 3);
            const int col = nt * 8 + (lane & 3) * 2 + (rr & 1);
            red[wrp * 512 + lr * 32 + col] = acc[nt][rr];
        }
    }
    __syncthreads();

    #pragma unroll
    for (int o = 0; o < 2; o++) {
        const int out = tid + 512 * o;
        const int d = out >> 5, e = out & 31;
        const int hh = d >> 4, lr = d & 15;
        float s = 0.f;
        #pragma unroll
        for (int ww = 0; ww < 8; ww++)
            s += red[(8 * hh + ww) * 512 + lr * 32 + e];
        g_gram_part[(long)chunk * (BATCH*NHEADS*HD*HD) + bh * 1024 + out] = s;
    }

    sq += __shfl_xor_sync(0xffffffffu, sq, 1);
    sq += __shfl_xor_sync(0xffffffffu, sq, 2);
    sq += __shfl_xor_sync(0xffffffffu, sq, 4);
    if (grp == 0) {
        if (ch6 < 32)
            g_qsq_part[chunk * (BATCH*NHEADS*HD) + bh * HD + c] = sq;
        else
            g_ksq_part[chunk * (BATCH*NHEADS*HD) + bh * HD + c] = sq;
    }
}

// ---------------------------------------------------------------------------
// Depthwise conv for v -> split fp16 hi/lo in [b][ch][px]. 8 px per thread.
// ---------------------------------------------------------------------------
__global__ __launch_bounds__(256) void dwv(
    const __half* __restrict__ qkv, const float* __restrict__ wdw)
{
    const long idx = (long)blockIdx.x * 256 + threadIdx.x;   // < 2*192*8192
    const int px0   = (int)(idx & 8191) << 3;
    const int plane = (int)(idx >> 13);                      // b*192 + ch
    const int ch = plane % KDIM, b = plane / KDIM;
    const int gch = 2 * C_ + ch;

    const __half* in = qkv + ((long)b * C3 + gch) * HW_;
    float w[9];
    #pragma unroll
    for (int i = 0; i < 9; i++) w[i] = wdw[gch * 9 + i];

    const int y  = px0 >> 8;
    const int x0 = px0 & 255;
    float o[8];
    conv8h(in, w, y, x0, o);

    uint4 hi, lo;
    split8h(*reinterpret_cast<float4*>(o), *reinterpret_cast<float4*>(o + 4), hi, lo);
    const long off = (long)plane * HW_ + px0;
    *reinterpret_cast<uint4*>(g_v_h + off) = hi;
    *reinterpret_cast<uint4*>(g_v_l + off) = lo;
}

// split x (fp32 [b][192][HW]) -> fp16 hi/lo, same layout. 8 floats/thread.
__global__ __launch_bounds__(256) void split_x(const float* __restrict__ x)
{
    const long idx = (long)blockIdx.x * 256 + threadIdx.x;
    const long off = idx * 8;
    const float4 f0 = *reinterpret_cast<const float4*>(x + off);
    const float4 f1 = *reinterpret_cast<const float4*>(x + off + 4);
    uint4 hi, lo;
    split8h(f0, f1, hi, lo);
    *reinterpret_cast<uint4*>(g_x_h + off) = hi;
    *reinterpret_cast<uint4*>(g_x_l + off) = lo;
}

// w_qkv (576x192 fp32) -> A1 fp16 (padded 640x192)
__global__ __launch_bounds__(256) void split_w1(const float* __restrict__ w)
{
    const int i = blockIdx.x * 256 + threadIdx.x;
    g_A1[i] = __float2half_rn(w[i]);
}

// reduce + normalize + temperature + softmax
__global__ __launch_bounds__(1024) void attn_kernel(const float* __restrict__ temperature)
{
    const int bh = blockIdx.x;
    const int h = bh % NHEADS;
    const int e = threadIdx.x, d = threadIdx.y;

    float g = 0.f, qsq = 0.f, ksq = 0.f;
    #pragma unroll
    for (int ch = 0; ch < GR_CHUNKS; ch++) {
        g   += g_gram_part[(long)ch * (BATCH*NHEADS*HD*HD) + bh * 1024 + d * 32 + e];
        qsq += g_qsq_part[ch * (BATCH*NHEADS*HD) + bh * HD + d];
        ksq += g_ksq_part[ch * (BATCH*NHEADS*HD) + bh * HD + e];
    }
    const float t  = fminf(temperature[h], 5.0f);
    const float qn = fmaxf(sqrtf(qsq), 1e-12f);
    const float kn = fmaxf(sqrtf(ksq), 1e-12f);
    const float val = g / (qn * kn) * t;

    float m = val;
    #pragma unroll
    for (int o = 16; o > 0; o >>= 1) m = fmaxf(m, __shfl_xor_sync(0xffffffffu, m, o));
    const float p = expf(val - m);
    float s = p;
    #pragma unroll
    for (int o = 16; o > 0; o >>= 1) s += __shfl_xor_sync(0xffffffffu, s, o);

    g_attn[bh * 1024 + d * 32 + e] = p / s;
}

// M_eff = w_proj @ blockdiag(attn) -> fp16 A2 (padded 256x192/batch)
__global__ __launch_bounds__(256) void meff_kernel(const float* __restrict__ wproj)
{
    const int idx = blockIdx.x * 256 + threadIdx.x;
    const int bz  = blockIdx.y;
    const int o   = idx / C_;
    const int ce  = idx % C_;
    const int h   = ce >> 5, e = ce & 31;

    const float* ar = g_attn + (bz * NHEADS + h) * 1024 + e;
    const float* wr = wproj + o * C_ + h * 32;

    float s = 0.f;
    #pragma unroll
    for (int dd = 0; dd < 32; dd++) s += wr[dd] * ar[dd * 32];

    g_A2[(long)bz * M2PAD * KDIM + (long)o * KDIM + ce] = __float2half_rn(s);
}

// ---------------------------------------------------------------------------
extern "C" void kernel_launch(void* const* d_in, const int* in_sizes, int n_in,
                              void* d_out, int out_size)
{
    (void)in_sizes; (void)n_in; (void)out_size;
    const float* x      = (const float*)d_in[0];
    const float* w_qkv  = (const float*)d_in[1];
    const float* w_dw   = (const float*)d_in[2];
    const float* w_proj = (const float*)d_in[3];
    const float* temp   = (const float*)d_in[4];
    float* out = (float*)d_out;

    __half *qkvh, *xh, *xl, *vh, *vl, *a1, *a2;
    cudaGetSymbolAddress((void**)&qkvh, g_qkv_h);
    cudaGetSymbolAddress((void**)&xh, g_x_h);
    cudaGetSymbolAddress((void**)&xl, g_x_l);
    cudaGetSymbolAddress((void**)&vh, g_v_h);
    cudaGetSymbolAddress((void**)&vl, g_v_l);
    cudaGetSymbolAddress((void**)&a1, g_A1);
    cudaGetSymbolAddress((void**)&a2, g_A2);

    static bool attr_set = false;
    if (!attr_set) {
        cudaFuncSetAttribute(gemm_h2<true>,  cudaFuncAttributeMaxDynamicSharedMemorySize, GSMEM);
        cudaFuncSetAttribute(gemm_h2<false>, cudaFuncAttributeMaxDynamicSharedMemorySize, GSMEM);
        cudaFuncSetAttribute(dwgram, cudaFuncAttributeMaxDynamicSharedMemorySize, DG_SMEM);
        attr_set = true;
    }

    // 0) weight + x conversion
    split_w1<<<(M1 * KDIM) / 256, 256>>>(w_qkv);
    split_x<<<(int)(((long)BATCH * KDIM * HW_ / 8) / 256), 256>>>(x);

    // 1) qkv = w_qkv @ x  (fp16 2-product, fp16 output)
    gemm_h2<true><<<dim3(M1PAD / BM, HW_ / BN, BATCH), 256, GSMEM>>>(
        a1, xh, xl, qkvh, M1, 0L, (long)C3 * HW_);

    // 2) fused depthwise conv + single-fp16 tensor-core gram partials (q,k)
    dwgram<<<dim3(GR_CHUNKS, BATCH * NHEADS), 512, DG_SMEM>>>(qkvh, w_dw);

    // 3) depthwise conv v -> split fp16 [K][N]
    dwv<<<(int)(((long)BATCH * KDIM * HW_ / 8) / 256), 256>>>(qkvh, w_dw);

    // 4) softmax + proj-absorb
    attn_kernel<<<BATCH * NHEADS, dim3(32, 32)>>>(temp);
    meff_kernel<<<dim3((C_ * C_) / 256, BATCH), 256>>>(w_proj);

    // 5) out = M_eff @ v  (fp16 2-product, fp32 output)
    gemm_h2<false><<<dim3(M2PAD / BM, HW_ / BN, BATCH), 256, GSMEM>>>(
        a2, vh, vl, out, M2, (long)M2PAD * KDIM, (long)C_ * HW_);
}

// round 17
// speedup vs baseline: 1.2026x; 1.0835x over previous
#include <cuda_runtime.h>
#include <cuda_bf16.h>
#include <cuda_fp16.h>
#include <cstdint>

#define C_     192
#define C3     576
#define NHEADS 6
#define HD     32
#define HH_    256
#define WW_    256
#define HW_    65536
#define BATCH  2
#define KDIM   192
#define M1     576
#define M1PAD  640
#define M2     192
#define M2PAD  256

#define GR_CHUNKS 64           // 64 chunks x 4 rows = 256 image rows
#define ROWS_PC   4

// GEMM tiling (fp16: single A tile + B hi/lo; lo product optional per m-block)
#define BM 128
#define BN 128
#define BK 32
#define APITCH 80              // bytes per A smem row (64B data + 16B pad)
#define BPITCH 272             // bytes per B smem row (256B data + 16B pad)
#define ATILE (BM * APITCH)    // 10240
#define BTILE (BK * BPITCH)    // 8704
#define BUFSZ (ATILE + 2 * BTILE)      // 27648
#define GSMEM (2 * BUFSZ)              // 55296
#define NITER 6                        // 192/32 k-tiles

// dwgram tiles: 2 fp16 tiles [32ch][256px], pitch 528B (single-product gram)
#define QP_B 528
#define DG_SMEM (2 * 32 * QP_B)        // 33792 B

// ---------------- scratch (device globals) -----------------------------------
__device__ __half g_qkv_h[BATCH * C3 * HW_];          // qkv intermediate, fp16
__device__ __half g_x_h[BATCH * KDIM * HW_];          // [b][k][n] fp16 hi
__device__ __half g_x_l[BATCH * KDIM * HW_];          // fp16 lo
__device__ __half g_v_h[BATCH * KDIM * HW_];
__device__ __half g_v_l[BATCH * KDIM * HW_];
__device__ __half g_A1[M1PAD * KDIM];                 // w_qkv fp16 (padded rows zero)
__device__ __half g_A2[BATCH * M2PAD * KDIM];         // M_eff fp16
__device__ float g_gram_part[GR_CHUNKS * BATCH * NHEADS * HD * HD];
__device__ float g_qsq_part [GR_CHUNKS * BATCH * NHEADS * HD];
__device__ float g_ksq_part [GR_CHUNKS * BATCH * NHEADS * HD];
__device__ float g_attn[BATCH * NHEADS * HD * HD];

// ---------------- PTX helpers (sm_80+ only) ----------------------------------
__device__ __forceinline__ uint32_t smem_u32(const void* p) {
    uint32_t a;
    asm("{ .reg .u64 t; cvta.to.shared.u64 t, %1; cvt.u32.u64 %0, t; }" : "=r"(a) : "l"(p));
    return a;
}
#define CP_ASYNC16(dst, src) \
    asm volatile("cp.async.cg.shared.global [%0], [%1], 16;" :: "r"(dst), "l"(src))
#define CP_COMMIT() asm volatile("cp.async.commit_group;" ::: "memory")
#define CP_WAIT(n)  asm volatile("cp.async.wait_group %0;" :: "n"(n) : "memory")

#define LDM_X4(r, addr) \
    asm volatile("ldmatrix.sync.aligned.m8n8.x4.shared.b16 {%0,%1,%2,%3}, [%4];" \
        : "=r"((r)[0]), "=r"((r)[1]), "=r"((r)[2]), "=r"((r)[3]) : "r"(addr))
#define LDM_X2T(r, addr) \
    asm volatile("ldmatrix.sync.aligned.m8n8.x2.trans.shared.b16 {%0,%1}, [%2];" \
        : "=r"((r)[0]), "=r"((r)[1]) : "r"(addr))

// fp16 mma
__device__ __forceinline__ void mma16816h(float* d, const uint32_t* a, const uint32_t* b) {
    asm volatile(
        "mma.sync.aligned.m16n8k16.row.col.f32.f16.f16.f32 "
        "{%0,%1,%2,%3}, {%4,%5,%6,%7}, {%8,%9}, {%0,%1,%2,%3};"
        : "+f"(d[0]), "+f"(d[1]), "+f"(d[2]), "+f"(d[3])
        : "r"(a[0]), "r"(a[1]), "r"(a[2]), "r"(a[3]), "r"(b[0]), "r"(b[1]));
}

// pack 8 fp32 -> 8 fp16 hi (uint4) + 8 fp16 lo (uint4)
__device__ __forceinline__ void split8h(const float4& a, const float4& b, uint4& hi, uint4& lo) {
    float f[8] = {a.x, a.y, a.z, a.w, b.x, b.y, b.z, b.w};
    uint32_t ph[4], pl[4];
    #pragma unroll
    for (int i = 0; i < 4; i++) {
        const __half h0 = __float2half_rn(f[2*i]);
        const __half h1 = __float2half_rn(f[2*i+1]);
        __half2 th = __halves2half2(h0, h1);
        ph[i] = *reinterpret_cast<uint32_t*>(&th);
        __half2 tl = __halves2half2(__float2half_rn(f[2*i]   - __half2float(h0)),
                                    __float2half_rn(f[2*i+1] - __half2float(h1)));
        pl[i] = *reinterpret_cast<uint32_t*>(&tl);
    }
    hi = make_uint4(ph[0], ph[1], ph[2], ph[3]);
    lo = make_uint4(pl[0], pl[1], pl[2], pl[3]);
}

// ---------------------------------------------------------------------------
// fp16 GEMM: C = A*B.  A fp16 [M][192]; B fp16 hi/lo [192][HW].
// m-blocks >= loFrom use 2 products (A*Bh + A*Bl); earlier blocks use A*Bh only
// (precision-insensitive q,k rows). HALF_OUT selects fp16 vs fp32 C.
// ---------------------------------------------------------------------------
template <bool HALF_OUT>
__global__ __launch_bounds__(256, 2) void gemm_h2(
    const __half* __restrict__ A,
    const __half* __restrict__ Bh, const __half* __restrict__ Bl,
    void* __restrict__ Cv, int Mvalid, long aBatch, long cBatch, int loFrom)
{
    extern __shared__ char smem[];
    const uint32_t sb = smem_u32(smem);

    const int tid  = threadIdx.x;
    const int wid  = tid >> 5;
    const int lane = tid & 31;
    const int wm   = wid >> 2;       // 0..1  (64 rows)
    const int wn   = wid & 3;        // 0..3  (32 cols)

    const int bz = blockIdx.z;
    const int m0 = blockIdx.x * BM;
    const int n0 = blockIdx.y * BN;
    const bool two = ((int)blockIdx.x >= loFrom);

    A  += (long)bz * aBatch;
    Bh += (long)bz * KDIM * HW_;  Bl += (long)bz * KDIM * HW_;

    float acc[4][4][4];
    #pragma unroll
    for (int i = 0; i < 4; i++)
        #pragma unroll
        for (int j = 0; j < 4; j++)
            #pragma unroll
            for (int r = 0; r < 4; r++) acc[i][j][r] = 0.f;

    auto loadTiles = [&](int it, int buf) {
        const int k0 = it * BK;
        const uint32_t base = sb + (uint32_t)buf * BUFSZ;
        #pragma unroll
        for (int i = 0; i < 2; i++) {
            const int ca = tid + 256 * i;          // 0..511
            const int ar = ca >> 2, as_ = ca & 3;
            CP_ASYNC16(base + ar * APITCH + as_ * 16,
                       A + (long)(m0 + ar) * KDIM + k0 + as_ * 8);
            const int br = ca >> 4, bs_ = ca & 15;
            const long gob = (long)(k0 + br) * HW_ + n0 + bs_ * 8;
            const uint32_t sofb = br * BPITCH + bs_ * 16;
            CP_ASYNC16(base + ATILE + sofb, Bh + gob);
            if (two)
                CP_ASYNC16(base + ATILE + BTILE + sofb, Bl + gob);
        }
    };

    loadTiles(0, 0);
    CP_COMMIT();

    #pragma unroll 1
    for (int it = 0; it < NITER; it++) {
        if (it + 1 < NITER) {
            loadTiles(it + 1, (it + 1) & 1);
            CP_COMMIT();
            CP_WAIT(1);
        } else {
            CP_WAIT(0);
        }
        __syncthreads();

        const uint32_t base = sb + (uint32_t)(it & 1) * BUFSZ;
        const uint32_t aB  = base;
        const uint32_t bHb = base + ATILE, bLb = bHb + BTILE;

        #pragma unroll
        for (int kf = 0; kf < 2; kf++) {
            uint32_t a[4][4], bH[4][2], bL[4][2];
            #pragma unroll
            for (int i = 0; i < 4; i++) {
                const uint32_t ro = (uint32_t)(wm * 64 + i * 16 + (lane & 15)) * APITCH
                                  + kf * 32 + ((lane >> 4) << 4);
                LDM_X4(a[i], aB + ro);
            }
            #pragma unroll
            for (int j = 0; j < 4; j++) {
                const uint32_t ro = (uint32_t)(kf * 16 + (lane & 15)) * BPITCH
                                  + (uint32_t)(wn * 32 + j * 8) * 2;
                LDM_X2T(bH[j], bHb + ro);
            }
            if (two) {
                #pragma unroll
                for (int j = 0; j < 4; j++) {
                    const uint32_t ro = (uint32_t)(kf * 16 + (lane & 15)) * BPITCH
                                      + (uint32_t)(wn * 32 + j * 8) * 2;
                    LDM_X2T(bL[j], bLb + ro);
                }
                #pragma unroll
                for (int i = 0; i < 4; i++)
                    #pragma unroll
                    for (int j = 0; j < 4; j++) {
                        mma16816h(acc[i][j], a[i], bH[j]);
                        mma16816h(acc[i][j], a[i], bL[j]);
                    }
            } else {
                #pragma unroll
                for (int i = 0; i < 4; i++)
                    #pragma unroll
                    for (int j = 0; j < 4; j++)
                        mma16816h(acc[i][j], a[i], bH[j]);
            }
        }
        __syncthreads();
    }

    const int rw = m0 + wm * 64 + (lane >> 2);
    const int cw = n0 + wn * 32 + (lane & 3) * 2;
    if (HALF_OUT) {
        __half* C = reinterpret_cast<__half*>(Cv) + (long)bz * cBatch;
        #pragma unroll
        for (int i = 0; i < 4; i++) {
            #pragma unroll
            for (int j = 0; j < 4; j++) {
                const int row = rw + i * 16;
                const int col = cw + j * 8;
                if (row < Mvalid)
                    *reinterpret_cast<__half2*>(C + (long)row * HW_ + col) =
                        __halves2half2(__float2half_rn(acc[i][j][0]),
                                       __float2half_rn(acc[i][j][1]));
                if (row + 8 < Mvalid)
                    *reinterpret_cast<__half2*>(C + (long)(row + 8) * HW_ + col) =
                        __halves2half2(__float2half_rn(acc[i][j][2]),
                                       __float2half_rn(acc[i][j][3]));
            }
        }
    } else {
        float* C = reinterpret_cast<float*>(Cv) + (long)bz * cBatch;
        #pragma unroll
        for (int i = 0; i < 4; i++) {
            #pragma unroll
            for (int j = 0; j < 4; j++) {
                const int row = rw + i * 16;
                const int col = cw + j * 8;
                if (row < Mvalid)
                    *reinterpret_cast<float2*>(C + (long)row * HW_ + col) =
                        make_float2(acc[i][j][0], acc[i][j][1]);
                if (row + 8 < Mvalid)
                    *reinterpret_cast<float2*>(C + (long)(row + 8) * HW_ + col) =
                        make_float2(acc[i][j][2], acc[i][j][3]);
            }
        }
    }
}

// ---------------------------------------------------------------------------
// 4-pixel depthwise conv over fp16 plane: rows y-1..y+1, x0 % 4 == 0
// ---------------------------------------------------------------------------
__device__ __forceinline__ void conv4h(
    const __half* __restrict__ plane, const float* __restrict__ w,
    int y, int x0, float out[4])
{
    out[0] = out[1] = out[2] = out[3] = 0.f;
    #pragma unroll
    for (int dy = -1; dy <= 1; dy++) {
        const int yy = y + dy;
        if (yy < 0 || yy >= HH_) continue;
        const __half* row = plane + yy * WW_ + x0;
        const uint2 u = *reinterpret_cast<const uint2*>(row);   // 8B aligned
        const __half2 h01 = *reinterpret_cast<const __half2*>(&u.x);
        const __half2 h23 = *reinterpret_cast<const __half2*>(&u.y);
        const float m0 = __low2float(h01), m1 = __high2float(h01);
        const float m2 = __low2float(h23), m3 = __high2float(h23);
        const float lft = (x0 > 0)       ? __half2float(row[-1]) : 0.f;
        const float rgt = (x0 + 4 < 256) ? __half2float(row[4])  : 0.f;
        const float w0 = w[(dy + 1) * 3 + 0];
        const float w1 = w[(dy + 1) * 3 + 1];
        const float w2 = w[(dy + 1) * 3 + 2];
        out[0] += w0 * lft + w1 * m0 + w2 * m1;
        out[1] += w0 * m0  + w1 * m1 + w2 * m2;
        out[2] += w0 * m1  + w1 * m2 + w2 * m3;
        out[3] += w0 * m2  + w1 * m3 + w2 * rgt;
    }
}

// ---------------------------------------------------------------------------
// 8-pixel depthwise conv over fp16 plane (dwv; x0 % 8 == 0 -> 16B aligned)
// ---------------------------------------------------------------------------
__device__ __forceinline__ void conv8h(
    const __half* __restrict__ plane, const float* __restrict__ w,
    int y, int x0, float out[8])
{
    #pragma unroll
    for (int i = 0; i < 8; i++) out[i] = 0.f;
    #pragma unroll
    for (int dy = -1; dy <= 1; dy++) {
        const int yy = y + dy;
        if (yy < 0 || yy >= HH_) continue;
        const __half* row = plane + yy * WW_ + x0;
        const uint4 u = *reinterpret_cast<const uint4*>(row);
        const __half2 p0 = *reinterpret_cast<const __half2*>(&u.x);
        const __half2 p1 = *reinterpret_cast<const __half2*>(&u.y);
        const __half2 p2 = *reinterpret_cast<const __half2*>(&u.z);
        const __half2 p3 = *reinterpret_cast<const __half2*>(&u.w);
        float m[8] = {__low2float(p0), __high2float(p0), __low2float(p1), __high2float(p1),
                      __low2float(p2), __high2float(p2), __low2float(p3), __high2float(p3)};
        const float lft = (x0 > 0)       ? __half2float(row[-1]) : 0.f;
        const float rgt = (x0 + 8 < 256) ? __half2float(row[8])  : 0.f;
        const float w0 = w[(dy + 1) * 3 + 0];
        const float w1 = w[(dy + 1) * 3 + 1];
        const float w2 = w[(dy + 1) * 3 + 2];
        out[0] += w0 * lft  + w1 * m[0] + w2 * m[1];
        #pragma unroll
        for (int i = 1; i < 7; i++)
            out[i] += w0 * m[i-1] + w1 * m[i] + w2 * m[i+1];
        out[7] += w0 * m[6] + w1 * m[7] + w2 * rgt;
    }
}

// ---------------------------------------------------------------------------
// Fused depthwise conv (q,k) + single-fp16 tensor-core Gram partials.
// ---------------------------------------------------------------------------
__global__ __launch_bounds__(512, 2) void dwgram(
    const __half* __restrict__ qkv, const float* __restrict__ wdw)
{
    extern __shared__ char smraw[];
    const uint32_t sb = smem_u32(smraw);
    const uint32_t qhb = sb;
    const uint32_t khb = sb + 32 * QP_B;
    float* red = reinterpret_cast<float*>(smraw);   // reused after last mma

    const int bh = blockIdx.y;
    const int b = bh / NHEADS, h = bh % NHEADS;
    const int chunk = blockIdx.x;
    const int tid = threadIdx.x;
    const int lane = tid & 31;

    // conv mapping: 64 channels x 8 x-groups (interleaved 4-px tasks)
    const int ch6 = tid >> 3;
    const int grp = tid & 7;
    const int c   = ch6 & 31;
    const int gch = (ch6 < 32) ? (h * HD + c) : (C_ + h * HD + c);
    const __half* plane = qkv + ((long)b * C3 + gch) * HW_;
    float w[9];
    #pragma unroll
    for (int i = 0; i < 9; i++) w[i] = wdw[gch * 9 + i];
    const uint32_t dHo = (ch6 < 32 ? 0u : 32u * QP_B) + (uint32_t)c * QP_B;

    // gram warp mapping
    const int wrp  = tid >> 5;
    const int half = wrp >> 3;
    const int slc  = wrp & 7;

    float acc[4][4];
    #pragma unroll
    for (int j = 0; j < 4; j++)
        #pragma unroll
        for (int r = 0; r < 4; r++) acc[j][r] = 0.f;
    float sq = 0.f;

    #pragma unroll 1
    for (int r = 0; r < ROWS_PC; r++) {
        const int y = chunk * ROWS_PC + r;
        __syncthreads();
        #pragma unroll
        for (int i = 0; i < 8; i++) {
            const int x0 = (grp + 8 * i) * 4;
            float o[4];
            conv4h(plane, w, y, x0, o);
            sq += o[0]*o[0] + o[1]*o[1] + o[2]*o[2] + o[3]*o[3];
            __half2 t0 = __halves2half2(__float2half_rn(o[0]), __float2half_rn(o[1]));
            __half2 t1 = __halves2half2(__float2half_rn(o[2]), __float2half_rn(o[3]));
            uint2 ph;
            ph.x = *reinterpret_cast<uint32_t*>(&t0);
            ph.y = *reinterpret_cast<uint32_t*>(&t1);
            *reinterpret_cast<uint2*>(smraw + dHo + x0 * 2) = ph;
        }
        __syncthreads();

        // gram mma over this row's 256 px: warp handles 32-px slice
        #pragma unroll
        for (int c2 = 0; c2 < 2; c2++) {
            const uint32_t off = (uint32_t)(slc * 64 + c2 * 32);
            uint32_t aH[4], bH[2][4];
            const uint32_t ra = (uint32_t)(16 * half + (lane & 15)) * QP_B
                              + ((lane >> 4) << 4) + off;
            LDM_X4(aH, qhb + ra);
            #pragma unroll
            for (int nt2 = 0; nt2 < 2; nt2++) {
                const uint32_t rb = (uint32_t)((lane & 7) + ((lane >> 4) << 3) + 16 * nt2) * QP_B
                                  + (((lane >> 3) & 1) << 4) + off;
                LDM_X4(bH[nt2], khb + rb);
            }
            #pragma unroll
            for (int nt = 0; nt < 4; nt++)
                mma16816h(acc[nt], aH, &bH[nt >> 1][(nt & 1) * 2]);
        }
    }

    // reduce 16 warp-partials -> 32x32
    __syncthreads();
    #pragma unroll
    for (int nt = 0; nt < 4; nt++) {
        #pragma unroll
        for (int rr = 0; rr < 4; rr++) {
            const int lr  = (lane >> 2) + ((rr >> 1) << 3);
            const int col = nt * 8 + (lane & 3) * 2 + (rr & 1);
            red[wrp * 512 + lr * 32 + col] = acc[nt][rr];
        }
    }
    __syncthreads();

    #pragma unroll
    for (int o = 0; o < 2; o++) {
        const int out = tid + 512 * o;
        const int d = out >> 5, e = out & 31;
        const int hh = d >> 4, lr = d & 15;
        float s = 0.f;
        #pragma unroll
        for (int ww = 0; ww < 8; ww++)
            s += red[(8 * hh + ww) * 512 + lr * 32 + e];
        g_gram_part[(long)chunk * (BATCH*NHEADS*HD*HD) + bh * 1024 + out] = s;
    }

    sq += __shfl_xor_sync(0xffffffffu, sq, 1);
    sq += __shfl_xor_sync(0xffffffffu, sq, 2);
    sq += __shfl_xor_sync(0xffffffffu, sq, 4);
    if (grp == 0) {
        if (ch6 < 32)
            g_qsq_part[chunk * (BATCH*NHEADS*HD) + bh * HD + c] = sq;
        else
            g_ksq_part[chunk * (BATCH*NHEADS*HD) + bh * HD + c] = sq;
    }
}

// ---------------------------------------------------------------------------
// Depthwise conv for v -> split fp16 hi/lo in [b][ch][px]. 8 px per thread.
// ---------------------------------------------------------------------------
__global__ __launch_bounds__(256) void dwv(
    const __half* __restrict__ qkv, const float* __restrict__ wdw)
{
    const long idx = (long)blockIdx.x * 256 + threadIdx.x;   // < 2*192*8192
    const int px0   = (int)(idx & 8191) << 3;
    const int plane = (int)(idx >> 13);                      // b*192 + ch
    const int ch = plane % KDIM, b = plane / KDIM;
    const int gch = 2 * C_ + ch;

    const __half* in = qkv + ((long)b * C3 + gch) * HW_;
    float w[9];
    #pragma unroll
    for (int i = 0; i < 9; i++) w[i] = wdw[gch * 9 + i];

    const int y  = px0 >> 8;
    const int x0 = px0 & 255;
    float o[8];
    conv8h(in, w, y, x0, o);

    uint4 hi, lo;
    split8h(*reinterpret_cast<float4*>(o), *reinterpret_cast<float4*>(o + 4), hi, lo);
    const long off = (long)plane * HW_ + px0;
    *reinterpret_cast<uint4*>(g_v_h + off) = hi;
    *reinterpret_cast<uint4*>(g_v_l + off) = lo;
}

// split x (fp32 [b][192][HW]) -> fp16 hi/lo, same layout. 8 floats/thread.
__global__ __launch_bounds__(256) void split_x(const float* __restrict__ x)
{
    const long idx = (long)blockIdx.x * 256 + threadIdx.x;
    const long off = idx * 8;
    const float4 f0 = *reinterpret_cast<const float4*>(x + off);
    const float4 f1 = *reinterpret_cast<const float4*>(x + off + 4);
    uint4 hi, lo;
    split8h(f0, f1, hi, lo);
    *reinterpret_cast<uint4*>(g_x_h + off) = hi;
    *reinterpret_cast<uint4*>(g_x_l + off) = lo;
}

// w_qkv (576x192 fp32) -> A1 fp16 (padded 640x192)
__global__ __launch_bounds__(256) void split_w1(const float* __restrict__ w)
{
    const int i = blockIdx.x * 256 + threadIdx.x;
    g_A1[i] = __float2half_rn(w[i]);
}

// reduce + normalize + temperature + softmax
__global__ __launch_bounds__(1024) void attn_kernel(const float* __restrict__ temperature)
{
    const int bh = blockIdx.x;
    const int h = bh % NHEADS;
    const int e = threadIdx.x, d = threadIdx.y;

    float g = 0.f, qsq = 0.f, ksq = 0.f;
    #pragma unroll
    for (int ch = 0; ch < GR_CHUNKS; ch++) {
        g   += g_gram_part[(long)ch * (BATCH*NHEADS*HD*HD) + bh * 1024 + d * 32 + e];
        qsq += g_qsq_part[ch * (BATCH*NHEADS*HD) + bh * HD + d];
        ksq += g_ksq_part[ch * (BATCH*NHEADS*HD) + bh * HD + e];
    }
    const float t  = fminf(temperature[h], 5.0f);
    const float qn = fmaxf(sqrtf(qsq), 1e-12f);
    const float kn = fmaxf(sqrtf(ksq), 1e-12f);
    const float val = g / (qn * kn) * t;

    float m = val;
    #pragma unroll
    for (int o = 16; o > 0; o >>= 1) m = fmaxf(m, __shfl_xor_sync(0xffffffffu, m, o));
    const float p = expf(val - m);
    float s = p;
    #pragma unroll
    for (int o = 16; o > 0; o >>= 1) s += __shfl_xor_sync(0xffffffffu, s, o);

    g_attn[bh * 1024 + d * 32 + e] = p / s;
}

// M_eff = w_proj @ blockdiag(attn) -> fp16 A2 (padded 256x192/batch)
__global__ __launch_bounds__(256) void meff_kernel(const float* __restrict__ wproj)
{
    const int idx = blockIdx.x * 256 + threadIdx.x;
    const int bz  = blockIdx.y;
    const int o   = idx / C_;
    const int ce  = idx % C_;
    const int h   = ce >> 5, e = ce & 31;

    const float* ar = g_attn + (bz * NHEADS + h) * 1024 + e;
    const float* wr = wproj + o * C_ + h * 32;

    float s = 0.f;
    #pragma unroll
    for (int dd = 0; dd < 32; dd++) s += wr[dd] * ar[dd * 32];

    g_A2[(long)bz * M2PAD * KDIM + (long)o * KDIM + ce] = __float2half_rn(s);
}

// ---------------------------------------------------------------------------
extern "C" void kernel_launch(void* const* d_in, const int* in_sizes, int n_in,
                              void* d_out, int out_size)
{
    (void)in_sizes; (void)n_in; (void)out_size;
    const float* x      = (const float*)d_in[0];
    const float* w_qkv  = (const float*)d_in[1];
    const float* w_dw   = (const float*)d_in[2];
    const float* w_proj = (const float*)d_in[3];
    const float* temp   = (const float*)d_in[4];
    float* out = (float*)d_out;

    __half *qkvh, *xh, *xl, *vh, *vl, *a1, *a2;
    cudaGetSymbolAddress((void**)&qkvh, g_qkv_h);
    cudaGetSymbolAddress((void**)&xh, g_x_h);
    cudaGetSymbolAddress((void**)&xl, g_x_l);
    cudaGetSymbolAddress((void**)&vh, g_v_h);
    cudaGetSymbolAddress((void**)&vl, g_v_l);
    cudaGetSymbolAddress((void**)&a1, g_A1);
    cudaGetSymbolAddress((void**)&a2, g_A2);

    static bool attr_set = false;
    if (!attr_set) {
        cudaFuncSetAttribute(gemm_h2<true>,  cudaFuncAttributeMaxDynamicSharedMemorySize, GSMEM);
        cudaFuncSetAttribute(gemm_h2<false>, cudaFuncAttributeMaxDynamicSharedMemorySize, GSMEM);
        cudaFuncSetAttribute(dwgram, cudaFuncAttributeMaxDynamicSharedMemorySize, DG_SMEM);
        attr_set = true;
    }

    // 0) weight + x conversion
    split_w1<<<(M1 * KDIM) / 256, 256>>>(w_qkv);
    split_x<<<(int)(((long)BATCH * KDIM * HW_ / 8) / 256), 256>>>(x);

    // 1) qkv = w_qkv @ x  (q,k rows: 1 product; v rows (m-blocks >= 3): 2 products)
    gemm_h2<true><<<dim3(M1PAD / BM, HW_ / BN, BATCH), 256, GSMEM>>>(
        a1, xh, xl, qkvh, M1, 0L, (long)C3 * HW_, 3);

    // 2) fused depthwise conv + single-fp16 tensor-core gram partials (q,k)
    dwgram<<<dim3(GR_CHUNKS, BATCH * NHEADS), 512, DG_SMEM>>>(qkvh, w_dw);

    // 3) depthwise conv v -> split fp16 [K][N]
    dwv<<<(int)(((long)BATCH * KDIM * HW_ / 8) / 256), 256>>>(qkvh, w_dw);

    // 4) softmax + proj-absorb
    attn_kernel<<<BATCH * NHEADS, dim3(32, 32)>>>(temp);
    meff_kernel<<<dim3((C_ * C_) / 256, BATCH), 256>>>(w_proj);

    // 5) out = M_eff @ v  (all 2-product: output precision matters)
    gemm_h2<false><<<dim3(M2PAD / BM, HW_ / BN, BATCH), 256, GSMEM>>>(
        a2, vh, vl, out, M2, (long)M2PAD * KDIM, (long)C_ * HW_, 0);
}